// round 10
// baseline (speedup 1.0000x reference)
#include <cuda_runtime.h>
#include <cuda_bf16.h>
#include <cstdint>
#include <cstddef>

#define B_ 4
#define T_ 8192
#define DIM_ 512
#define DIM2_ 256
#define H_ 8
#define D_ 64
#define C_ 64
#define N_ 128
#define BH_ 32
#define EPSV 1.1920929e-07f
#define MAX_LR 0.01f

// ---------------- scratch (static device globals; no allocations) ----------------
__device__ float g_s  [(size_t)B_*T_*DIM_];     // rmsnorm(seq) fp32 (for proj)
__device__ uint32_t g_shp[(size_t)B_*T_*DIM2_]; // rmsnorm(seq) bf16x2 hi (k-paired)
__device__ uint32_t g_slp[(size_t)B_*T_*DIM2_]; // bf16x2 lo
__device__ float g_kv [(size_t)B_*T_*2*DIM_];   // [k | v]
__device__ float g_q  [(size_t)B_*T_*DIM_];     // s @ Wq
__device__ float g_g1 [(size_t)BH_*N_*D_*D_];   // -grad w1 -> W1eff after scan
__device__ float g_g2 [(size_t)BH_*N_*D_*D_];   // -grad w2 -> W2eff after scan
__device__ uint32_t g_vhp[(size_t)B_*T_*DIM2_]; // merged vals bf16x2 hi
__device__ uint32_t g_vlp[(size_t)B_*T_*DIM2_]; // bf16x2 lo
__device__ float g_lr  [(size_t)B_*T_*H_];
__device__ float g_gate[(size_t)B_*T_*H_];
__device__ float g_mom [(size_t)B_*N_*H_];
__device__ float g_dec [(size_t)B_*N_*H_];
// preconverted big-GEMM weights, bf16x2 k-paired hi/lo
__device__ uint32_t g_wkvh[DIM2_*2*DIM_], g_wkvl[DIM2_*2*DIM_];
__device__ uint32_t g_wqh [DIM2_*DIM_],   g_wql [DIM2_*DIM_];
__device__ uint32_t g_wch [DIM2_*DIM_],   g_wcl [DIM2_*DIM_];

// ---- bf16 64x64 buffer geometry: [64 rows][36 u32] (72 bf16, contraction dim contiguous)
#define BLD2 36
#define BUFB (64 * BLD2)          // u32 per buffer
// w1/w2 pre-laid-out for chunk_grad: [W1t_h, W1t_l, W2t_h, W2t_l, W2n_h, W2n_l]
__device__ uint32_t g_w1w2bf[6 * BUFB];

__device__ __forceinline__ float sigmoidf_(float x) { return 1.f / (1.f + expf(-x)); }

__device__ __forceinline__ float bf16f(float x) {
    return __bfloat162float(__float2bfloat16(x));
}

// pack two floats to bf16x2: e0 -> low 16 bits, e1 -> high
__device__ __forceinline__ uint32_t pack_bf2(float e0, float e1) {
    uint32_t r;
    asm("cvt.rn.bf16x2.f32 %0, %1, %2;" : "=r"(r) : "f"(e1), "f"(e0));
    return r;
}

__device__ __forceinline__ void mma_bf16(float c[4], const uint32_t a[4],
                                         uint32_t b0, uint32_t b1) {
    asm volatile(
        "mma.sync.aligned.m16n8k16.row.col.f32.bf16.bf16.f32 "
        "{%0,%1,%2,%3},{%4,%5,%6,%7},{%8,%9},{%0,%1,%2,%3};"
        : "+f"(c[0]), "+f"(c[1]), "+f"(c[2]), "+f"(c[3])
        : "r"(a[0]), "r"(a[1]), "r"(a[2]), "r"(a[3]), "r"(b0), "r"(b1));
}

__device__ __forceinline__ void cp16(uint32_t dst, const void* src) {
    asm volatile("cp.async.ca.shared.global [%0], [%1], 16;" :: "r"(dst), "l"(src));
}

// ---------------- K1: rmsnorm over dim=512, emits fp32 + packed bf16 hi/lo ----------------
__global__ __launch_bounds__(256) void rmsnorm_kernel(const float* __restrict__ seq) {
    size_t row = blockIdx.x;
    const float2* in2 = (const float2*)(seq + row * DIM_);
    int tid = threadIdx.x;
    float2 v = in2[tid];
    float ss = v.x * v.x + v.y * v.y;
#pragma unroll
    for (int o = 16; o; o >>= 1) ss += __shfl_xor_sync(0xffffffffu, ss, o);
    __shared__ float wsum[8];
    if ((tid & 31) == 0) wsum[tid >> 5] = ss;
    __syncthreads();
    float tot = 0.f;
#pragma unroll
    for (int w = 0; w < 8; w++) tot += wsum[w];
    float sc = rsqrtf(tot * (1.f / DIM_) + EPSV);
    float o0 = v.x * sc, o1 = v.y * sc;
    ((float2*)(g_s + row * DIM_))[tid] = make_float2(o0, o1);
    size_t pb = row * DIM2_ + tid;
    g_shp[pb] = pack_bf2(o0, o1);
    g_slp[pb] = pack_bf2(o0 - bf16f(o0), o1 - bf16f(o1));
}

// ---------------- weight preconvert (big GEMMs): pack along K into bf16x2 hi/lo ----------------
__global__ void cvtpack_kernel(const float* __restrict__ src, uint32_t* __restrict__ dh,
                               uint32_t* __restrict__ dl, int K2, int N) {
    int i = blockIdx.x * 256 + threadIdx.x;
    if (i < K2 * N) {
        int k2 = i / N, n = i - k2 * N;
        float e0 = src[(size_t)(2 * k2) * N + n];
        float e1 = src[(size_t)(2 * k2 + 1) * N + n];
        dh[i] = pack_bf2(e0, e1);
        dl[i] = pack_bf2(e0 - bf16f(e0), e1 - bf16f(e1));
    }
}

// ---------------- prep w1/w2 layouts for chunk_grad ----------------
__global__ void prep_w_kernel(const float* __restrict__ w1, const float* __restrict__ w2) {
    int idx = blockIdx.x * 256 + threadIdx.x;
    if (idx < 4096) {
        int r = idx >> 6, c = idx & 63;
        __nv_bfloat16* base = (__nv_bfloat16*)g_w1w2bf;
        const int HB = 2 * BUFB;   // halves per buffer
        float v1 = w1[idx];
        float h1 = bf16f(v1);
        base[0 * HB + c * 72 + r] = __float2bfloat16(v1);
        base[1 * HB + c * 72 + r] = __float2bfloat16(v1 - h1);
        float v2 = w2[idx];
        float h2 = bf16f(v2);
        base[2 * HB + c * 72 + r] = __float2bfloat16(v2);        // W2t [c][r]
        base[3 * HB + c * 72 + r] = __float2bfloat16(v2 - h2);
        base[4 * HB + r * 72 + c] = __float2bfloat16(v2);        // W2n [r][c]
        base[5 * HB + r * 72 + c] = __float2bfloat16(v2 - h2);
    }
}

// ---------------- K2: per-token lr/gate projections + per-chunk mom/decay ----------------
__global__ __launch_bounds__(256) void proj_kernel(const float* __restrict__ Wstep,
                                                   const float* __restrict__ Wgate,
                                                   const float* __restrict__ Wmom,
                                                   const float* __restrict__ Wdecay) {
    int blk = blockIdx.x;              // b*N_ + nn
    int b = blk >> 7, nn = blk & 127;
    size_t tb = (size_t)b * T_ + (size_t)nn * C_;
    int tid = threadIdx.x, lane = tid & 31, w = tid >> 5;

    for (int tk = w; tk < C_; tk += 8) {
        const float* srow = g_s + (tb + tk) * DIM_;
        float acc[16];
#pragma unroll
        for (int q = 0; q < 16; q++) acc[q] = 0.f;
        for (int p = lane; p < DIM_; p += 32) {
            float sv = srow[p];
            const float* ws = Wstep + p * H_;
            const float* wg = Wgate + p * H_;
#pragma unroll
            for (int hh = 0; hh < 8; hh++) {
                acc[hh]     += sv * ws[hh];
                acc[8 + hh] += sv * wg[hh];
            }
        }
#pragma unroll
        for (int q = 0; q < 16; q++)
#pragma unroll
            for (int o = 16; o; o >>= 1) acc[q] += __shfl_xor_sync(0xffffffffu, acc[q], o);
        if (lane == 0) {
#pragma unroll
            for (int hh = 0; hh < 8; hh++) {
                g_lr  [(tb + tk) * H_ + hh] = sigmoidf_(acc[hh]) * MAX_LR;
                g_gate[(tb + tk) * H_ + hh] = sigmoidf_(acc[8 + hh]);
            }
        }
    }

    __shared__ float ssum[DIM_];
    for (int p = tid; p < DIM_; p += 256) {
        float a = 0.f;
        for (int tk = 0; tk < C_; tk++) a += g_s[(tb + tk) * DIM_ + p];
        ssum[p] = a * (1.f / C_);
    }
    __syncthreads();
    if (w < 8) {
        float am = 0.f, ad = 0.f;
        for (int p = lane; p < DIM_; p += 32) {
            am += ssum[p] * Wmom[p * H_ + w];
            ad += ssum[p] * Wdecay[p * H_ + w];
        }
#pragma unroll
        for (int o = 16; o; o >>= 1) {
            am += __shfl_xor_sync(0xffffffffu, am, o);
            ad += __shfl_xor_sync(0xffffffffu, ad, o);
        }
        if (lane == 0) {
            g_mom[((size_t)b * N_ + nn) * H_ + w] = sigmoidf_(am);
            g_dec[((size_t)b * N_ + nn) * H_ + w] = sigmoidf_(ad);
        }
    }
}

// ---------------- gemm_bf16 (unchanged from R8) ----------------
#define GA_LD 20
#define GB_LD 136
#define GA_SZ (128 * GA_LD)
#define GB_SZ (16 * GB_LD)
#define GSTAGE (2 * GA_SZ + 2 * GB_SZ)
#define GEMM_SMEM (2 * GSTAGE * 4)

__device__ __forceinline__ void gemm_issue(uint32_t sbase, const uint32_t* __restrict__ Ah,
                                           const uint32_t* __restrict__ Al,
                                           const uint32_t* __restrict__ Bh,
                                           const uint32_t* __restrict__ Bl,
                                           int brow, int bcol, int kt2, int K2, int N, int tid) {
    int ra = tid >> 2, ca = (tid & 3) << 2;
    int rb = tid >> 5, cb = (tid & 31) << 2;
#pragma unroll
    for (int p = 0; p < 2; p++) {
        int r = p * 64 + ra;
        size_t ga = (size_t)(brow + r) * K2 + kt2 + ca;
        uint32_t da = sbase + (r * GA_LD + ca) * 4;
        cp16(da, Ah + ga);
        cp16(da + GA_SZ * 4, Al + ga);
        int r2 = p * 8 + rb;
        size_t gb = (size_t)(kt2 + r2) * N + bcol + cb;
        uint32_t db = sbase + (2 * GA_SZ + r2 * GB_LD + cb) * 4;
        cp16(db, Bh + gb);
        cp16(db + GB_SZ * 4, Bl + gb);
    }
}

__global__ __launch_bounds__(256) void gemm_bf16(const uint32_t* __restrict__ Ah,
                                                 const uint32_t* __restrict__ Al,
                                                 const uint32_t* __restrict__ Bh,
                                                 const uint32_t* __restrict__ Bl,
                                                 float* __restrict__ C,
                                                 int M, int N, int K2) {
    extern __shared__ uint32_t smem_u[];
    int tid = threadIdx.x;
    int lane = tid & 31, warp = tid >> 5;
    int brow = blockIdx.y * 128, bcol = blockIdx.x * 128;
    int wm = (warp >> 1) * 32, wn = (warp & 1) * 64;
    int g = lane >> 2, tg = lane & 3;
    uint32_t sbase = (uint32_t)__cvta_generic_to_shared(smem_u);

    float acc[2][8][4];
#pragma unroll
    for (int mi = 0; mi < 2; mi++)
#pragma unroll
        for (int ni = 0; ni < 8; ni++)
#pragma unroll
            for (int e = 0; e < 4; e++) acc[mi][ni][e] = 0.f;

    gemm_issue(sbase, Ah, Al, Bh, Bl, brow, bcol, 0, K2, N, tid);
    asm volatile("cp.async.commit_group;");

    int KT = K2 >> 4;
    for (int t = 0; t < KT; t++) {
        if (t + 1 < KT) {
            gemm_issue(sbase + ((t + 1) & 1) * GSTAGE * 4, Ah, Al, Bh, Bl,
                       brow, bcol, (t + 1) << 4, K2, N, tid);
            asm volatile("cp.async.commit_group;");
            asm volatile("cp.async.wait_group 1;");
        } else {
            asm volatile("cp.async.wait_group 0;");
        }
        __syncthreads();
        const uint32_t* st = smem_u + (t & 1) * GSTAGE;
        const uint32_t* sAh = st;
        const uint32_t* sAl = st + GA_SZ;
        const uint32_t* sBh = st + 2 * GA_SZ;
        const uint32_t* sBl = st + 2 * GA_SZ + GB_SZ;
#pragma unroll
        for (int kh = 0; kh < 2; kh++) {
            int k8 = kh * 8;
            uint32_t ah[2][4], al[2][4];
#pragma unroll
            for (int mi = 0; mi < 2; mi++) {
                int r0 = (wm + mi * 16 + g) * GA_LD + k8 + tg;
                int r1 = r0 + 8 * GA_LD;
                ah[mi][0] = sAh[r0];     ah[mi][1] = sAh[r1];
                ah[mi][2] = sAh[r0 + 4]; ah[mi][3] = sAh[r1 + 4];
                al[mi][0] = sAl[r0];     al[mi][1] = sAl[r1];
                al[mi][2] = sAl[r0 + 4]; al[mi][3] = sAl[r1 + 4];
            }
#pragma unroll
            for (int ni = 0; ni < 8; ni++) {
                int nb = (k8 + tg) * GB_LD + wn + ni * 8 + g;
                uint32_t bh0 = sBh[nb], bh1 = sBh[nb + 4 * GB_LD];
                uint32_t bl0 = sBl[nb], bl1 = sBl[nb + 4 * GB_LD];
#pragma unroll
                for (int mi = 0; mi < 2; mi++) {
                    mma_bf16(acc[mi][ni], ah[mi], bh0, bh1);
                    mma_bf16(acc[mi][ni], ah[mi], bl0, bl1);
                    mma_bf16(acc[mi][ni], al[mi], bh0, bh1);
                }
            }
        }
        __syncthreads();
    }

#pragma unroll
    for (int mi = 0; mi < 2; mi++)
#pragma unroll
        for (int ni = 0; ni < 8; ni++) {
            int r = brow + wm + mi * 16 + g;
            int cx = bcol + wn + ni * 8 + tg * 2;
            float2 lo = {acc[mi][ni][0], acc[mi][ni][1]};
            float2 hi = {acc[mi][ni][2], acc[mi][ni][3]};
            *(float2*)(C + (size_t)r * N + cx) = lo;
            *(float2*)(C + (size_t)(r + 8) * N + cx) = hi;
        }
}

// ---------------- 64x64x64 bf16 3-term mm: A [m][k2] LD36, B [n][k2] LD36 ----------------
__device__ __forceinline__ void mm64_bf(const uint32_t* __restrict__ Ah,
                                        const uint32_t* __restrict__ Al,
                                        const uint32_t* __restrict__ Bh,
                                        const uint32_t* __restrict__ Bl,
                                        float acc[4][4], int m0, int n0, int g, int tg) {
#pragma unroll
    for (int ni = 0; ni < 4; ni++)
#pragma unroll
        for (int e = 0; e < 4; e++) acc[ni][e] = 0.f;
#pragma unroll
    for (int s = 0; s < 4; s++) {
        int kc = s * 8 + tg;
        uint32_t ah[4], al[4];
        int ra = (m0 + g) * BLD2 + kc;
        ah[0] = Ah[ra]; ah[1] = Ah[ra + 8 * BLD2]; ah[2] = Ah[ra + 4]; ah[3] = Ah[ra + 8 * BLD2 + 4];
        al[0] = Al[ra]; al[1] = Al[ra + 8 * BLD2]; al[2] = Al[ra + 4]; al[3] = Al[ra + 8 * BLD2 + 4];
#pragma unroll
        for (int ni = 0; ni < 4; ni++) {
            int rb = (n0 + ni * 8 + g) * BLD2 + kc;
            uint32_t bh0 = Bh[rb], bh1 = Bh[rb + 4];
            uint32_t bl0 = Bl[rb], bl1 = Bl[rb + 4];
            mma_bf16(acc[ni], ah, bh0, bh1);
            mma_bf16(acc[ni], ah, bl0, bl1);
            mma_bf16(acc[ni], al, bh0, bh1);
        }
    }
}

// fragment (row, col): e0=(g,2tg) e1=(g,2tg+1) e2=(g+8,2tg) e3=(g+8,2tg+1)

// ---------------- K4: per-chunk MLP gradients (bf16 3-term, dual layouts) ----------------
#define CG_SMEM (16 * BUFB * 4)
__global__ __launch_bounds__(256) void chunk_grad_bf() {
    int id = blockIdx.x;               // bh*N_ + nn
    int bh = id >> 7, nn = id & 127;
    int b = bh >> 3, h = bh & 7;
    size_t tb = (size_t)b * T_ + (size_t)nn * C_;
    extern __shared__ uint32_t smu[];
    uint32_t* KCp_h = smu;               uint32_t* KCp_l = smu + BUFB;
    uint32_t* KCt_h = smu + 2 * BUFB;    uint32_t* KCt_l = smu + 3 * BUFB;
    uint32_t* W1t_h = smu + 4 * BUFB;    uint32_t* W1t_l = smu + 5 * BUFB;   // -> HHp
    uint32_t* W2t_h = smu + 6 * BUFB;    uint32_t* W2t_l = smu + 7 * BUFB;   // -> DX1t
    uint32_t* W2n_h = smu + 8 * BUFB;    uint32_t* W2n_l = smu + 9 * BUFB;
    uint32_t* HHt_h = smu + 10 * BUFB;   uint32_t* HHt_l = smu + 11 * BUFB;
    uint32_t* G2p_h = smu + 12 * BUFB;   uint32_t* G2p_l = smu + 13 * BUFB;
    uint32_t* G2t_h = smu + 14 * BUFB;   uint32_t* G2t_l = smu + 15 * BUFB;
    __shared__ float lrs[64];
    int tid = threadIdx.x;
    if (tid < 64) lrs[tid] = g_lr[(tb + tid) * H_ + h];

    // weights: straight u32 copy into slots 4..9
    for (int t = tid; t < 6 * BUFB; t += 256) smu[4 * BUFB + t] = g_w1w2bf[t];

    // KC: fp32 load -> bf16 hi/lo into natural + transposed layouts
    {
        __nv_bfloat16* kph = (__nv_bfloat16*)KCp_h;
        __nv_bfloat16* kpl = (__nv_bfloat16*)KCp_l;
        __nv_bfloat16* kth = (__nv_bfloat16*)KCt_h;
        __nv_bfloat16* ktl = (__nv_bfloat16*)KCt_l;
        for (int idx = tid; idx < 4096; idx += 256) {
            int i = idx >> 6, j = idx & 63;
            float kc = g_kv[(tb + i) * (2 * DIM_) + h * 64 + j];
            float hv = bf16f(kc);
            __nv_bfloat16 hb = __float2bfloat16(kc);
            __nv_bfloat16 lb = __float2bfloat16(kc - hv);
            kph[i * 72 + j] = hb; kpl[i * 72 + j] = lb;
            kth[j * 72 + i] = hb; ktl[j * 72 + i] = lb;
        }
    }
    __syncthreads();
    int lane = tid & 31, warp = tid >> 5;
    int m0 = (warp >> 1) * 16, n0 = (warp & 1) * 32;
    int g = lane >> 2, tg = lane & 3;
    float acc[4][4], x1s[4][4];

    // MM1: X1 = KC @ W1 (B = W1t). X1 stays in regs; HH = silu(X1)
    mm64_bf(KCp_h, KCp_l, W1t_h, W1t_l, acc, m0, n0, g, tg);
    __syncthreads();   // all warps done reading W1t before HHp overwrite
    {
        uint32_t* HHp_h = W1t_h;
        uint32_t* HHp_l = W1t_l;
        __nv_bfloat16* hth = (__nv_bfloat16*)HHt_h;
        __nv_bfloat16* htl = (__nv_bfloat16*)HHt_l;
#pragma unroll
        for (int ni = 0; ni < 4; ni++) {
            int col = n0 + ni * 8 + 2 * tg;
            float v[4], hv[4], lv[4];
#pragma unroll
            for (int e = 0; e < 4; e++) {
                float x = acc[ni][e];
                x1s[ni][e] = x;
                v[e] = x * sigmoidf_(x);
                hv[e] = bf16f(v[e]);
                lv[e] = v[e] - hv[e];
            }
            int r0 = m0 + g, r1 = m0 + 8 + g, c2 = col >> 1;
            HHp_h[r0 * BLD2 + c2] = pack_bf2(v[0], v[1]);
            HHp_l[r0 * BLD2 + c2] = pack_bf2(lv[0], lv[1]);
            HHp_h[r1 * BLD2 + c2] = pack_bf2(v[2], v[3]);
            HHp_l[r1 * BLD2 + c2] = pack_bf2(lv[2], lv[3]);
            hth[col * 72 + r0] = __float2bfloat16(v[0]);       htl[col * 72 + r0] = __float2bfloat16(lv[0]);
            hth[(col + 1) * 72 + r0] = __float2bfloat16(v[1]); htl[(col + 1) * 72 + r0] = __float2bfloat16(lv[1]);
            hth[col * 72 + r1] = __float2bfloat16(v[2]);       htl[col * 72 + r1] = __float2bfloat16(lv[2]);
            hth[(col + 1) * 72 + r1] = __float2bfloat16(v[3]); htl[(col + 1) * 72 + r1] = __float2bfloat16(lv[3]);
        }
    }
    __syncthreads();

    // MM2: X2 = HH @ W2 (B = W2t) ; G2 = (2 lr / 64)(X2 - v)
    mm64_bf(W1t_h, W1t_l, W2t_h, W2t_l, acc, m0, n0, g, tg);
    {
        __nv_bfloat16* gth = (__nv_bfloat16*)G2t_h;
        __nv_bfloat16* gtl = (__nv_bfloat16*)G2t_l;
#pragma unroll
        for (int ni = 0; ni < 4; ni++) {
            int col = n0 + ni * 8 + 2 * tg;
            float v[4], lv[4];
            int rr[4] = {m0 + g, m0 + g, m0 + 8 + g, m0 + 8 + g};
#pragma unroll
            for (int e = 0; e < 4; e++) {
                int row = rr[e], cc = col + (e & 1);
                float vc = g_kv[(tb + row) * (2 * DIM_) + DIM_ + h * 64 + cc];
                v[e] = (2.f / 64.f) * lrs[row] * (acc[ni][e] - vc);
                lv[e] = v[e] - bf16f(v[e]);
            }
            int r0 = m0 + g, r1 = m0 + 8 + g, c2 = col >> 1;
            G2p_h[r0 * BLD2 + c2] = pack_bf2(v[0], v[1]);
            G2p_l[r0 * BLD2 + c2] = pack_bf2(lv[0], lv[1]);
            G2p_h[r1 * BLD2 + c2] = pack_bf2(v[2], v[3]);
            G2p_l[r1 * BLD2 + c2] = pack_bf2(lv[2], lv[3]);
            gth[col * 72 + r0] = __float2bfloat16(v[0]);       gtl[col * 72 + r0] = __float2bfloat16(lv[0]);
            gth[(col + 1) * 72 + r0] = __float2bfloat16(v[1]); gtl[(col + 1) * 72 + r0] = __float2bfloat16(lv[1]);
            gth[col * 72 + r1] = __float2bfloat16(v[2]);       gtl[col * 72 + r1] = __float2bfloat16(lv[2]);
            gth[(col + 1) * 72 + r1] = __float2bfloat16(v[3]); gtl[(col + 1) * 72 + r1] = __float2bfloat16(lv[3]);
        }
    }
    __syncthreads();

    // MM3: g2 = HH^T @ G2  (A = HHt, B = G2t) -> store -g2
    mm64_bf(HHt_h, HHt_l, G2t_h, G2t_l, acc, m0, n0, g, tg);
    size_t gbase = (size_t)id * 4096;
#pragma unroll
    for (int ni = 0; ni < 4; ni++) {
        int col = n0 + ni * 8 + 2 * tg;
        float2 v0 = {-acc[ni][0], -acc[ni][1]};
        float2 v1 = {-acc[ni][2], -acc[ni][3]};
        *(float2*)(g_g2 + gbase + (m0 + g) * 64 + col) = v0;
        *(float2*)(g_g2 + gbase + (m0 + 8 + g) * 64 + col) = v1;
    }

    // MM4: DX1 = (G2 @ W2^T) * silu'(X1)   (A = G2p, B = W2n) -> DX1t into W2t slots
    mm64_bf(G2p_h, G2p_l, W2n_h, W2n_l, acc, m0, n0, g, tg);
    {
        __nv_bfloat16* dth = (__nv_bfloat16*)W2t_h;
        __nv_bfloat16* dtl = (__nv_bfloat16*)W2t_l;
#pragma unroll
        for (int ni = 0; ni < 4; ni++) {
            int col = n0 + ni * 8 + 2 * tg;
            int rr[4] = {m0 + g, m0 + g, m0 + 8 + g, m0 + 8 + g};
#pragma unroll
            for (int e = 0; e < 4; e++) {
                int row = rr[e], cc = col + (e & 1);
                float x = x1s[ni][e];
                float sg = sigmoidf_(x);
                float dv = acc[ni][e] * sg * (1.f + x * (1.f - sg));
                float hv = bf16f(dv);
                dth[cc * 72 + row] = __float2bfloat16(dv);
                dtl[cc * 72 + row] = __float2bfloat16(dv - hv);
            }
        }
    }
    __syncthreads();

    // MM5: g1 = KC^T @ DX1  (A = KCt, B = DX1t) -> store -g1
    mm64_bf(KCt_h, KCt_l, W2t_h, W2t_l, acc, m0, n0, g, tg);
#pragma unroll
    for (int ni = 0; ni < 4; ni++) {
        int col = n0 + ni * 8 + 2 * tg;
        float2 v0 = {-acc[ni][0], -acc[ni][1]};
        float2 v1 = {-acc[ni][2], -acc[ni][3]};
        *(float2*)(g_g1 + gbase + (m0 + g) * 64 + col) = v0;
        *(float2*)(g_g1 + gbase + (m0 + 8 + g) * 64 + col) = v1;
    }
}

// ---------------- K5: double assoc-scan over n=128 chunks ----------------
__global__ __launch_bounds__(256) void scan_kernel(const float* __restrict__ w1,
                                                   const float* __restrict__ w2) {
    int bh = blockIdx.y;
    int idx = blockIdx.x * 256 + threadIdx.x;
    int b = bh >> 3, h = bh & 7;
    float w1v = w1[idx], w2v = w2[idx];
    float m1 = 0.f, u1 = 0.f, m2 = 0.f, u2 = 0.f;
    size_t base = ((size_t)bh * N_) * 4096 + idx;
    for (int nn = 0; nn < N_; nn++) {
        float mg = g_mom[((size_t)b * N_ + nn) * H_ + h];
        float dc = g_dec[((size_t)b * N_ + nn) * H_ + h];
        size_t off = base + (size_t)nn * 4096;
        float s1 = g_g1[off], s2 = g_g2[off];
        m1 = mg * m1 + s1; u1 = (1.f - dc) * u1 + m1; g_g1[off] = w1v + u1;
        m2 = mg * m2 + s2; u2 = (1.f - dc) * u2 + m2; g_g2[off] = w2v + u2;
    }
}

// ---------------- zero first 63 rows of packed vals per batch ----------------
__global__ void zero_pad_kernel() {
    int idx = blockIdx.x * 256 + threadIdx.x;
    const int per = 63 * DIM2_;
    if (idx < B_ * per) {
        int b = idx / per, r = idx % per;
        g_vhp[(size_t)b * T_ * DIM2_ + r] = 0u;
        g_vlp[(size_t)b * T_ * DIM2_ + r] = 0u;
    }
}

// ---------------- K6: retrieve (bf16 3-term) ----------------
#define RT_SMEM (6 * BUFB * 4)
__global__ __launch_bounds__(256) void retrieve_bf(const float* __restrict__ gamma) {
    int id = blockIdx.x;
    int bh = id >> 7, nn = id & 127;
    int b = bh >> 3, h = bh & 7;
    extern __shared__ uint32_t smu[];
    uint32_t* Qp_h  = smu;               uint32_t* Qp_l  = smu + BUFB;
    uint32_t* W1T_h = smu + 2 * BUFB;    uint32_t* W1T_l = smu + 3 * BUFB;  // -> HHp
    uint32_t* W2T_h = smu + 4 * BUFB;    uint32_t* W2T_l = smu + 5 * BUFB;
    __shared__ float rowp[64][2];
    __shared__ float gam[64];
    __shared__ float rscale[64];
    int tid = threadIdx.x;
    int j0 = nn * C_;
    size_t gbase = (size_t)id * 4096;
    if (tid < 64) gam[tid] = gamma[h * 64 + tid] + 1.f;
    {
        __nv_bfloat16* qh = (__nv_bfloat16*)Qp_h;
        __nv_bfloat16* ql = (__nv_bfloat16*)Qp_l;
        __nv_bfloat16* w1h = (__nv_bfloat16*)W1T_h;
        __nv_bfloat16* w1l = (__nv_bfloat16*)W1T_l;
        __nv_bfloat16* w2h = (__nv_bfloat16*)W2T_h;
        __nv_bfloat16* w2l = (__nv_bfloat16*)W2T_l;
        for (int idx = tid; idx < 4096; idx += 256) {
            int ci = idx >> 6, a = idx & 63;
            int i = j0 + ci + 63;
            float qv = (i < T_) ? g_q[((size_t)b * T_ + i) * DIM_ + h * 64 + a] : 0.f;
            qh[ci * 72 + a] = __float2bfloat16(qv);
            ql[ci * 72 + a] = __float2bfloat16(qv - bf16f(qv));
            // B of MM1: W1eff^T [col][row]; g_g1 idx = row(ci)*64 + col(a)
            float e1 = g_g1[gbase + idx];
            w1h[a * 72 + ci] = __float2bfloat16(e1);
            w1l[a * 72 + ci] = __float2bfloat16(e1 - bf16f(e1));
            float e2 = g_g2[gbase + idx];
            w2h[a * 72 + ci] = __float2bfloat16(e2);
            w2l[a * 72 + ci] = __float2bfloat16(e2 - bf16f(e2));
        }
    }
    __syncthreads();
    int lane = tid & 31, warp = tid >> 5;
    int m0 = (warp >> 1) * 16, n0 = (warp & 1) * 32;
    int g = lane >> 2, tg = lane & 3;
    float acc[4][4];

    // MM1: X1 = Q @ W1eff ; HH = silu(X1) -> overwrite W1T slots (packed pairs)
    mm64_bf(Qp_h, Qp_l, W1T_h, W1T_l, acc, m0, n0, g, tg);
    __syncthreads();
#pragma unroll
    for (int ni = 0; ni < 4; ni++) {
        int col = n0 + ni * 8 + 2 * tg;
        float v[4], lv[4];
#pragma unroll
        for (int e = 0; e < 4; e++) {
            float x = acc[ni][e];
            v[e] = x * sigmoidf_(x);
            lv[e] = v[e] - bf16f(v[e]);
        }
        int r0 = m0 + g, r1 = m0 + 8 + g, c2 = col >> 1;
        W1T_h[r0 * BLD2 + c2] = pack_bf2(v[0], v[1]);
        W1T_l[r0 * BLD2 + c2] = pack_bf2(lv[0], lv[1]);
        W1T_h[r1 * BLD2 + c2] = pack_bf2(v[2], v[3]);
        W1T_l[r1 * BLD2 + c2] = pack_bf2(lv[2], lv[3]);
    }
    __syncthreads();

    // MM2: Y = HH @ W2eff (stays in acc)
    mm64_bf(W1T_h, W1T_l, W2T_h, W2T_l, acc, m0, n0, g, tg);

    // per-row sum of squares via shfl over tg lanes
    float ss0 = 0.f, ss1 = 0.f;
#pragma unroll
    for (int ni = 0; ni < 4; ni++) {
        ss0 += acc[ni][0] * acc[ni][0] + acc[ni][1] * acc[ni][1];
        ss1 += acc[ni][2] * acc[ni][2] + acc[ni][3] * acc[ni][3];
    }
#pragma unroll
    for (int o = 1; o < 4; o <<= 1) {
        ss0 += __shfl_xor_sync(0xffffffffu, ss0, o);
        ss1 += __shfl_xor_sync(0xffffffffu, ss1, o);
    }
    if (tg == 0) {
        rowp[m0 + g][warp & 1] = ss0;
        rowp[m0 + 8 + g][warp & 1] = ss1;
    }
    __syncthreads();
    if (tid < 64) {
        int i = j0 + tid + 63;
        float gate = (i < T_) ? g_gate[((size_t)b * T_ + i) * H_ + h] : 0.f;
        float tot = rowp[tid][0] + rowp[tid][1];
        rscale[tid] = rsqrtf(tot * (1.f / 64.f) + EPSV) * gate;
    }
    __syncthreads();

    // scale + gamma, emit packed bf16 hi/lo vals (adjacent column pairs)
#pragma unroll
    for (int ni = 0; ni < 4; ni++) {
        int col = n0 + ni * 8 + 2 * tg;
        float ga0 = gam[col], ga1 = gam[col + 1];
#pragma unroll
        for (int half = 0; half < 2; half++) {
            int row = m0 + g + half * 8;
            int i = j0 + row + 63;
            if (i < T_) {
                float rs = rscale[row];
                float v0 = acc[ni][half * 2 + 0] * rs * ga0;
                float v1 = acc[ni][half * 2 + 1] * rs * ga1;
                size_t oidx = ((size_t)b * T_ + i) * DIM2_ + ((h * 64 + col) >> 1);
                g_vhp[oidx] = pack_bf2(v0, v1);
                g_vlp[oidx] = pack_bf2(v0 - bf16f(v0), v1 - bf16f(v1));
            }
        }
    }
}

// ---------------- launch ----------------
extern "C" void kernel_launch(void* const* d_in, const int* in_sizes, int n_in,
                              void* d_out, int out_size) {
    const float* seq      = (const float*)d_in[0];
    const float* w1       = (const float*)d_in[1];
    const float* w2       = (const float*)d_in[2];
    const float* Wq       = (const float*)d_in[3];
    const float* Wkv      = (const float*)d_in[4];
    const float* Wstep    = (const float*)d_in[5];
    const float* Wmom     = (const float*)d_in[6];
    const float* Wdecay   = (const float*)d_in[7];
    const float* Wgate    = (const float*)d_in[8];
    const float* Wcombine = (const float*)d_in[9];
    const float* gamma    = (const float*)d_in[10];
    float* out = (float*)d_out;
    (void)in_sizes; (void)n_in; (void)out_size;

    cudaFuncSetAttribute(gemm_bf16, cudaFuncAttributeMaxDynamicSharedMemorySize, GEMM_SMEM);
    cudaFuncSetAttribute(chunk_grad_bf, cudaFuncAttributeMaxDynamicSharedMemorySize, CG_SMEM);
    cudaFuncSetAttribute(retrieve_bf, cudaFuncAttributeMaxDynamicSharedMemorySize, RT_SMEM);

    uint32_t *p_shp, *p_slp, *p_vhp, *p_vlp;
    uint32_t *p_wkvh, *p_wkvl, *p_wqh, *p_wql, *p_wch, *p_wcl;
    float *p_kv, *p_q;
    cudaGetSymbolAddress((void**)&p_shp, g_shp);
    cudaGetSymbolAddress((void**)&p_slp, g_slp);
    cudaGetSymbolAddress((void**)&p_vhp, g_vhp);
    cudaGetSymbolAddress((void**)&p_vlp, g_vlp);
    cudaGetSymbolAddress((void**)&p_wkvh, g_wkvh);
    cudaGetSymbolAddress((void**)&p_wkvl, g_wkvl);
    cudaGetSymbolAddress((void**)&p_wqh, g_wqh);
    cudaGetSymbolAddress((void**)&p_wql, g_wql);
    cudaGetSymbolAddress((void**)&p_wch, g_wch);
    cudaGetSymbolAddress((void**)&p_wcl, g_wcl);
    cudaGetSymbolAddress((void**)&p_kv, g_kv);
    cudaGetSymbolAddress((void**)&p_q, g_q);

    rmsnorm_kernel<<<B_ * T_, 256>>>(seq);
    cvtpack_kernel<<<(DIM2_ * 2 * DIM_ + 255) / 256, 256>>>(Wkv, p_wkvh, p_wkvl, DIM2_, 2 * DIM_);
    cvtpack_kernel<<<(DIM2_ * DIM_ + 255) / 256, 256>>>(Wq, p_wqh, p_wql, DIM2_, DIM_);
    cvtpack_kernel<<<(DIM2_ * DIM_ + 255) / 256, 256>>>(Wcombine, p_wch, p_wcl, DIM2_, DIM_);
    prep_w_kernel<<<16, 256>>>(w1, w2);
    proj_kernel<<<B_ * N_, 256>>>(Wstep, Wgate, Wmom, Wdecay);
    gemm_bf16<<<dim3(2 * DIM_ / 128, B_ * T_ / 128), 256, GEMM_SMEM>>>(
        p_shp, p_slp, p_wkvh, p_wkvl, p_kv, B_ * T_, 2 * DIM_, DIM2_);
    gemm_bf16<<<dim3(DIM_ / 128, B_ * T_ / 128), 256, GEMM_SMEM>>>(
        p_shp, p_slp, p_wqh, p_wql, p_q, B_ * T_, DIM_, DIM2_);
    chunk_grad_bf<<<BH_ * N_, 256, CG_SMEM>>>();
    scan_kernel<<<dim3(16, BH_), 256>>>(w1, w2);
    zero_pad_kernel<<<(B_ * 63 * DIM2_ + 255) / 256, 256>>>();
    retrieve_bf<<<BH_ * N_, 256, RT_SMEM>>>(gamma);
    gemm_bf16<<<dim3(DIM_ / 128, B_ * T_ / 128), 256, GEMM_SMEM>>>(
        p_vhp, p_vlp, p_wch, p_wcl, out, B_ * T_, DIM_, DIM2_);
}

// round 11
// speedup vs baseline: 1.3432x; 1.3432x over previous
#include <cuda_runtime.h>
#include <cuda_bf16.h>
#include <cstdint>
#include <cstddef>

#define B_ 4
#define T_ 8192
#define DIM_ 512
#define DIM2_ 256
#define H_ 8
#define D_ 64
#define C_ 64
#define N_ 128
#define BH_ 32
#define EPSV 1.1920929e-07f
#define MAX_LR 0.01f

// ---------------- scratch (static device globals; no allocations) ----------------
__device__ float g_s  [(size_t)B_*T_*DIM_];     // rmsnorm(seq) fp32 (for proj)
__device__ uint32_t g_shp[(size_t)B_*T_*DIM2_]; // rmsnorm(seq) bf16x2 hi (k-paired)
__device__ uint32_t g_slp[(size_t)B_*T_*DIM2_]; // bf16x2 lo
__device__ float g_kv [(size_t)B_*T_*2*DIM_];   // [k | v]
__device__ float g_q  [(size_t)B_*T_*DIM_];     // s @ Wq
__device__ float g_g1 [(size_t)BH_*N_*D_*D_];   // -grad w1 -> W1eff after scan
__device__ float g_g2 [(size_t)BH_*N_*D_*D_];   // -grad w2 -> W2eff after scan
__device__ uint32_t g_vhp[(size_t)B_*T_*DIM2_]; // merged vals bf16x2 hi
__device__ uint32_t g_vlp[(size_t)B_*T_*DIM2_]; // bf16x2 lo
__device__ float g_lr  [(size_t)B_*T_*H_];
__device__ float g_gate[(size_t)B_*T_*H_];
__device__ float g_mom [(size_t)B_*N_*H_];
__device__ float g_dec [(size_t)B_*N_*H_];
// preconverted weights, bf16x2 k-paired hi/lo
__device__ uint32_t g_wkvh[DIM2_*2*DIM_], g_wkvl[DIM2_*2*DIM_];
__device__ uint32_t g_wqh [DIM2_*DIM_],   g_wql [DIM2_*DIM_];
__device__ uint32_t g_wch [DIM2_*DIM_],   g_wcl [DIM2_*DIM_];

__device__ __forceinline__ float sigmoidf_(float x) { return 1.f / (1.f + expf(-x)); }

__device__ __forceinline__ uint32_t f2tf(float x) {
    uint32_t r;
    asm("cvt.rna.tf32.f32 %0, %1;" : "=r"(r) : "f"(x));
    return r;
}

__device__ __forceinline__ float bf16f(float x) {
    return __bfloat162float(__float2bfloat16(x));
}

// pack two floats to bf16x2: e0 -> low 16 bits, e1 -> high
__device__ __forceinline__ uint32_t pack_bf2(float e0, float e1) {
    uint32_t r;
    asm("cvt.rn.bf16x2.f32 %0, %1, %2;" : "=r"(r) : "f"(e1), "f"(e0));
    return r;
}

__device__ __forceinline__ void mma_tf32(float c[4], const uint32_t a[4],
                                         uint32_t b0, uint32_t b1) {
    asm volatile(
        "mma.sync.aligned.m16n8k8.row.col.f32.tf32.tf32.f32 "
        "{%0,%1,%2,%3},{%4,%5,%6,%7},{%8,%9},{%0,%1,%2,%3};"
        : "+f"(c[0]), "+f"(c[1]), "+f"(c[2]), "+f"(c[3])
        : "r"(a[0]), "r"(a[1]), "r"(a[2]), "r"(a[3]), "r"(b0), "r"(b1));
}

__device__ __forceinline__ void mma_bf16(float c[4], const uint32_t a[4],
                                         uint32_t b0, uint32_t b1) {
    asm volatile(
        "mma.sync.aligned.m16n8k16.row.col.f32.bf16.bf16.f32 "
        "{%0,%1,%2,%3},{%4,%5,%6,%7},{%8,%9},{%0,%1,%2,%3};"
        : "+f"(c[0]), "+f"(c[1]), "+f"(c[2]), "+f"(c[3])
        : "r"(a[0]), "r"(a[1]), "r"(a[2]), "r"(a[3]), "r"(b0), "r"(b1));
}

__device__ __forceinline__ void cp16(uint32_t dst, const void* src) {
    asm volatile("cp.async.ca.shared.global [%0], [%1], 16;" :: "r"(dst), "l"(src));
}

// ---------------- K1: rmsnorm over dim=512, emits fp32 + packed bf16 hi/lo ----------------
__global__ __launch_bounds__(256) void rmsnorm_kernel(const float* __restrict__ seq) {
    size_t row = blockIdx.x;
    const float2* in2 = (const float2*)(seq + row * DIM_);
    int tid = threadIdx.x;
    float2 v = in2[tid];
    float ss = v.x * v.x + v.y * v.y;
#pragma unroll
    for (int o = 16; o; o >>= 1) ss += __shfl_xor_sync(0xffffffffu, ss, o);
    __shared__ float wsum[8];
    if ((tid & 31) == 0) wsum[tid >> 5] = ss;
    __syncthreads();
    float tot = 0.f;
#pragma unroll
    for (int w = 0; w < 8; w++) tot += wsum[w];
    float sc = rsqrtf(tot * (1.f / DIM_) + EPSV);
    float o0 = v.x * sc, o1 = v.y * sc;
    ((float2*)(g_s + row * DIM_))[tid] = make_float2(o0, o1);
    size_t pb = row * DIM2_ + tid;
    g_shp[pb] = pack_bf2(o0, o1);
    g_slp[pb] = pack_bf2(o0 - bf16f(o0), o1 - bf16f(o1));
}

// ---------------- weight preconvert: pack along K into bf16x2 hi/lo ----------------
__global__ void cvtpack_kernel(const float* __restrict__ src, uint32_t* __restrict__ dh,
                               uint32_t* __restrict__ dl, int K2, int N) {
    int i = blockIdx.x * 256 + threadIdx.x;
    if (i < K2 * N) {
        int k2 = i / N, n = i - k2 * N;
        float e0 = src[(size_t)(2 * k2) * N + n];
        float e1 = src[(size_t)(2 * k2 + 1) * N + n];
        dh[i] = pack_bf2(e0, e1);
        dl[i] = pack_bf2(e0 - bf16f(e0), e1 - bf16f(e1));
    }
}

// ---------------- K2: per-token lr/gate projections + per-chunk mom/decay ----------------
__global__ __launch_bounds__(256) void proj_kernel(const float* __restrict__ Wstep,
                                                   const float* __restrict__ Wgate,
                                                   const float* __restrict__ Wmom,
                                                   const float* __restrict__ Wdecay) {
    int blk = blockIdx.x;              // b*N_ + nn
    int b = blk >> 7, nn = blk & 127;
    size_t tb = (size_t)b * T_ + (size_t)nn * C_;
    int tid = threadIdx.x, lane = tid & 31, w = tid >> 5;

    for (int tk = w; tk < C_; tk += 8) {
        const float* srow = g_s + (tb + tk) * DIM_;
        float acc[16];
#pragma unroll
        for (int q = 0; q < 16; q++) acc[q] = 0.f;
        for (int p = lane; p < DIM_; p += 32) {
            float sv = srow[p];
            const float* ws = Wstep + p * H_;
            const float* wg = Wgate + p * H_;
#pragma unroll
            for (int hh = 0; hh < 8; hh++) {
                acc[hh]     += sv * ws[hh];
                acc[8 + hh] += sv * wg[hh];
            }
        }
#pragma unroll
        for (int q = 0; q < 16; q++)
#pragma unroll
            for (int o = 16; o; o >>= 1) acc[q] += __shfl_xor_sync(0xffffffffu, acc[q], o);
        if (lane == 0) {
#pragma unroll
            for (int hh = 0; hh < 8; hh++) {
                g_lr  [(tb + tk) * H_ + hh] = sigmoidf_(acc[hh]) * MAX_LR;
                g_gate[(tb + tk) * H_ + hh] = sigmoidf_(acc[8 + hh]);
            }
        }
    }

    __shared__ float ssum[DIM_];
    for (int p = tid; p < DIM_; p += 256) {
        float a = 0.f;
        for (int tk = 0; tk < C_; tk++) a += g_s[(tb + tk) * DIM_ + p];
        ssum[p] = a * (1.f / C_);
    }
    __syncthreads();
    if (w < 8) {
        float am = 0.f, ad = 0.f;
        for (int p = lane; p < DIM_; p += 32) {
            am += ssum[p] * Wmom[p * H_ + w];
            ad += ssum[p] * Wdecay[p * H_ + w];
        }
#pragma unroll
        for (int o = 16; o; o >>= 1) {
            am += __shfl_xor_sync(0xffffffffu, am, o);
            ad += __shfl_xor_sync(0xffffffffu, ad, o);
        }
        if (lane == 0) {
            g_mom[((size_t)b * N_ + nn) * H_ + w] = sigmoidf_(am);
            g_dec[((size_t)b * N_ + nn) * H_ + w] = sigmoidf_(ad);
        }
    }
}

// ---------------- gemm_bf16: cp.async double-buffered, 3-term bf16 split ----------------
// A packed [M][K2] u32 (bf16x2 along k), B packed [K2][N] u32, C fp32 [M][N]
#define GA_LD 20
#define GB_LD 136
#define GA_SZ (128 * GA_LD)
#define GB_SZ (16 * GB_LD)
#define GSTAGE (2 * GA_SZ + 2 * GB_SZ)
#define GEMM_SMEM (2 * GSTAGE * 4)

__device__ __forceinline__ void gemm_issue(uint32_t sbase, const uint32_t* __restrict__ Ah,
                                           const uint32_t* __restrict__ Al,
                                           const uint32_t* __restrict__ Bh,
                                           const uint32_t* __restrict__ Bl,
                                           int brow, int bcol, int kt2, int K2, int N, int tid) {
    int ra = tid >> 2, ca = (tid & 3) << 2;
    int rb = tid >> 5, cb = (tid & 31) << 2;
#pragma unroll
    for (int p = 0; p < 2; p++) {
        int r = p * 64 + ra;
        size_t ga = (size_t)(brow + r) * K2 + kt2 + ca;
        uint32_t da = sbase + (r * GA_LD + ca) * 4;
        cp16(da, Ah + ga);
        cp16(da + GA_SZ * 4, Al + ga);
        int r2 = p * 8 + rb;
        size_t gb = (size_t)(kt2 + r2) * N + bcol + cb;
        uint32_t db = sbase + (2 * GA_SZ + r2 * GB_LD + cb) * 4;
        cp16(db, Bh + gb);
        cp16(db + GB_SZ * 4, Bl + gb);
    }
}

__global__ __launch_bounds__(256, 2) void gemm_bf16(const uint32_t* __restrict__ Ah,
                                                    const uint32_t* __restrict__ Al,
                                                    const uint32_t* __restrict__ Bh,
                                                    const uint32_t* __restrict__ Bl,
                                                    float* __restrict__ C,
                                                    int M, int N, int K2) {
    extern __shared__ uint32_t smem_u[];
    int tid = threadIdx.x;
    int lane = tid & 31, warp = tid >> 5;
    int brow = blockIdx.y * 128, bcol = blockIdx.x * 128;
    int wm = (warp >> 1) * 32, wn = (warp & 1) * 64;
    int g = lane >> 2, tg = lane & 3;
    uint32_t sbase = (uint32_t)__cvta_generic_to_shared(smem_u);

    float acc[2][8][4];
#pragma unroll
    for (int mi = 0; mi < 2; mi++)
#pragma unroll
        for (int ni = 0; ni < 8; ni++)
#pragma unroll
            for (int e = 0; e < 4; e++) acc[mi][ni][e] = 0.f;

    gemm_issue(sbase, Ah, Al, Bh, Bl, brow, bcol, 0, K2, N, tid);
    asm volatile("cp.async.commit_group;");

    int KT = K2 >> 4;
    for (int t = 0; t < KT; t++) {
        if (t + 1 < KT) {
            gemm_issue(sbase + ((t + 1) & 1) * GSTAGE * 4, Ah, Al, Bh, Bl,
                       brow, bcol, (t + 1) << 4, K2, N, tid);
            asm volatile("cp.async.commit_group;");
            asm volatile("cp.async.wait_group 1;");
        } else {
            asm volatile("cp.async.wait_group 0;");
        }
        __syncthreads();
        const uint32_t* st = smem_u + (t & 1) * GSTAGE;
        const uint32_t* sAh = st;
        const uint32_t* sAl = st + GA_SZ;
        const uint32_t* sBh = st + 2 * GA_SZ;
        const uint32_t* sBl = st + 2 * GA_SZ + GB_SZ;
#pragma unroll
        for (int kh = 0; kh < 2; kh++) {
            int k8 = kh * 8;
            uint32_t ah[2][4], al[2][4];
#pragma unroll
            for (int mi = 0; mi < 2; mi++) {
                int r0 = (wm + mi * 16 + g) * GA_LD + k8 + tg;
                int r1 = r0 + 8 * GA_LD;
                ah[mi][0] = sAh[r0];     ah[mi][1] = sAh[r1];
                ah[mi][2] = sAh[r0 + 4]; ah[mi][3] = sAh[r1 + 4];
                al[mi][0] = sAl[r0];     al[mi][1] = sAl[r1];
                al[mi][2] = sAl[r0 + 4]; al[mi][3] = sAl[r1 + 4];
            }
#pragma unroll
            for (int ni = 0; ni < 8; ni++) {
                int nb = (k8 + tg) * GB_LD + wn + ni * 8 + g;
                uint32_t bh0 = sBh[nb], bh1 = sBh[nb + 4 * GB_LD];
                uint32_t bl0 = sBl[nb], bl1 = sBl[nb + 4 * GB_LD];
#pragma unroll
                for (int mi = 0; mi < 2; mi++) {
                    mma_bf16(acc[mi][ni], ah[mi], bh0, bh1);
                    mma_bf16(acc[mi][ni], ah[mi], bl0, bl1);
                    mma_bf16(acc[mi][ni], al[mi], bh0, bh1);
                }
            }
        }
        __syncthreads();
    }

#pragma unroll
    for (int mi = 0; mi < 2; mi++)
#pragma unroll
        for (int ni = 0; ni < 8; ni++) {
            int r = brow + wm + mi * 16 + g;
            int cx = bcol + wn + ni * 8 + tg * 2;
            float2 lo = {acc[mi][ni][0], acc[mi][ni][1]};
            float2 hi = {acc[mi][ni][2], acc[mi][ni][3]};
            *(float2*)(C + (size_t)r * N + cx) = lo;
            *(float2*)(C + (size_t)(r + 8) * N + cx) = hi;
        }
}

// ---------------- tensor-core 64x64x64 from smem tf32 hi/lo (3x split) ----------------
#define CLD 68
#define BUF (64 * CLD)

template <bool TA, bool TB>
__device__ __forceinline__ void mm64_tc(const uint32_t* __restrict__ Ah,
                                        const uint32_t* __restrict__ Al,
                                        const uint32_t* __restrict__ Bh,
                                        const uint32_t* __restrict__ Bl,
                                        float acc[4][4], int m0, int n0, int g, int tg) {
#pragma unroll
    for (int ni = 0; ni < 4; ni++)
#pragma unroll
        for (int e = 0; e < 4; e++) acc[ni][e] = 0.f;
#pragma unroll 2
    for (int k8 = 0; k8 < 64; k8 += 8) {
        uint32_t ah[4], al[4];
        if (!TA) {
            int ba = (m0 + g) * CLD + k8 + tg;
            ah[0] = Ah[ba]; ah[1] = Ah[ba + 8 * CLD]; ah[2] = Ah[ba + 4]; ah[3] = Ah[ba + 8 * CLD + 4];
            al[0] = Al[ba]; al[1] = Al[ba + 8 * CLD]; al[2] = Al[ba + 4]; al[3] = Al[ba + 8 * CLD + 4];
        } else {
            int ba = (k8 + tg) * CLD + m0 + g;
            ah[0] = Ah[ba]; ah[1] = Ah[ba + 8]; ah[2] = Ah[ba + 4 * CLD]; ah[3] = Ah[ba + 4 * CLD + 8];
            al[0] = Al[ba]; al[1] = Al[ba + 8]; al[2] = Al[ba + 4 * CLD]; al[3] = Al[ba + 4 * CLD + 8];
        }
#pragma unroll
        for (int ni = 0; ni < 4; ni++) {
            uint32_t bh0, bh1, bl0, bl1;
            if (!TB) {
                int bb = (k8 + tg) * CLD + n0 + ni * 8 + g;
                bh0 = Bh[bb]; bh1 = Bh[bb + 4 * CLD];
                bl0 = Bl[bb]; bl1 = Bl[bb + 4 * CLD];
            } else {
                int bb = (n0 + ni * 8 + g) * CLD + k8 + tg;
                bh0 = Bh[bb]; bh1 = Bh[bb + 4];
                bl0 = Bl[bb]; bl1 = Bl[bb + 4];
            }
            mma_tf32(acc[ni], ah, bh0, bh1);
            mma_tf32(acc[ni], ah, bl0, bl1);
            mma_tf32(acc[ni], al, bh0, bh1);
        }
    }
}

// fragment (row, col): e0=(g,2tg) e1=(g,2tg+1) e2=(g+8,2tg) e3=(g+8,2tg+1)
#define FRAG_ROW(e) (m0 + g + ((e) >> 1 ? 8 : 0))
#define FRAG_COL(ni, e) (n0 + (ni) * 8 + 2 * tg + ((e) & 1))

// ---------------- K4: per-chunk MLP gradients (tensor cores, 3x tf32) ----------------
#define CG_SMEM (9 * BUF * 4)
__global__ __launch_bounds__(256) void chunk_grad_tc(const float* __restrict__ w1,
                                                     const float* __restrict__ w2) {
    int id = blockIdx.x;               // bh*N_ + nn
    int bh = id >> 7, nn = id & 127;
    int b = bh >> 3, h = bh & 7;
    size_t tb = (size_t)b * T_ + (size_t)nn * C_;
    extern __shared__ uint32_t smu[];
    uint32_t* KCh = smu;
    uint32_t* KCl = smu + BUF;
    uint32_t* HHh = smu + 2 * BUF;     // holds W1 first, then HH, then DX1
    uint32_t* HHl = smu + 3 * BUF;
    uint32_t* W2h = smu + 4 * BUF;
    uint32_t* W2l = smu + 5 * BUF;
    float*    X1  = (float*)(smu + 6 * BUF);
    uint32_t* G2h = smu + 7 * BUF;
    uint32_t* G2l = smu + 8 * BUF;
    __shared__ float lrs[64];
    int tid = threadIdx.x;
    if (tid < 64) lrs[tid] = g_lr[(tb + tid) * H_ + h];
    for (int idx = tid; idx < 4096; idx += 256) {
        int i = idx >> 6, j = idx & 63;
        float kc = g_kv[(tb + i) * (2 * DIM_) + h * 64 + j];
        uint32_t hi = f2tf(kc);
        KCh[i * CLD + j] = hi; KCl[i * CLD + j] = f2tf(kc - __uint_as_float(hi));
        float a1 = w1[idx];
        hi = f2tf(a1);
        HHh[i * CLD + j] = hi; HHl[i * CLD + j] = f2tf(a1 - __uint_as_float(hi));
        float a2 = w2[idx];
        hi = f2tf(a2);
        W2h[i * CLD + j] = hi; W2l[i * CLD + j] = f2tf(a2 - __uint_as_float(hi));
    }
    __syncthreads();
    int lane = tid & 31, warp = tid >> 5;
    int m0 = (warp >> 1) * 16, n0 = (warp & 1) * 32;
    int g = lane >> 2, tg = lane & 3;
    float acc[4][4];

    // MM1: X1 = KC @ W1 ; HH = silu(X1)
    mm64_tc<false, false>(KCh, KCl, HHh, HHl, acc, m0, n0, g, tg);
    __syncthreads();
#pragma unroll
    for (int ni = 0; ni < 4; ni++)
#pragma unroll
        for (int e = 0; e < 4; e++) {
            int row = FRAG_ROW(e), col = FRAG_COL(ni, e);
            float x = acc[ni][e];
            X1[row * CLD + col] = x;
            float hv = x * sigmoidf_(x);
            uint32_t hi = f2tf(hv);
            HHh[row * CLD + col] = hi;
            HHl[row * CLD + col] = f2tf(hv - __uint_as_float(hi));
        }
    __syncthreads();

    // MM2: X2 = HH @ W2 ; G2 = (2 lr / 64)(X2 - v)
    mm64_tc<false, false>(HHh, HHl, W2h, W2l, acc, m0, n0, g, tg);
#pragma unroll
    for (int ni = 0; ni < 4; ni++)
#pragma unroll
        for (int e = 0; e < 4; e++) {
            int row = FRAG_ROW(e), col = FRAG_COL(ni, e);
            float vc = g_kv[(tb + row) * (2 * DIM_) + DIM_ + h * 64 + col];
            float gg = (2.f / 64.f) * lrs[row] * (acc[ni][e] - vc);
            uint32_t hi = f2tf(gg);
            G2h[row * CLD + col] = hi;
            G2l[row * CLD + col] = f2tf(gg - __uint_as_float(hi));
        }
    __syncthreads();

    // MM3: g2 = HH^T @ G2  -> store -g2
    mm64_tc<true, false>(HHh, HHl, G2h, G2l, acc, m0, n0, g, tg);
    size_t gbase = (size_t)id * 4096;
#pragma unroll
    for (int ni = 0; ni < 4; ni++) {
        int col = n0 + ni * 8 + 2 * tg;
        float2 v0 = {-acc[ni][0], -acc[ni][1]};
        float2 v1 = {-acc[ni][2], -acc[ni][3]};
        *(float2*)(g_g2 + gbase + (m0 + g) * 64 + col) = v0;
        *(float2*)(g_g2 + gbase + (m0 + 8 + g) * 64 + col) = v1;
    }
    __syncthreads();

    // MM4: DX1 = (G2 @ W2^T) * silu'(X1)  -> into HH bufs
    mm64_tc<false, true>(G2h, G2l, W2h, W2l, acc, m0, n0, g, tg);
#pragma unroll
    for (int ni = 0; ni < 4; ni++)
#pragma unroll
        for (int e = 0; e < 4; e++) {
            int row = FRAG_ROW(e), col = FRAG_COL(ni, e);
            float x = X1[row * CLD + col];
            float sg = sigmoidf_(x);
            float dv = acc[ni][e] * sg * (1.f + x * (1.f - sg));
            uint32_t hi = f2tf(dv);
            HHh[row * CLD + col] = hi;
            HHl[row * CLD + col] = f2tf(dv - __uint_as_float(hi));
        }
    __syncthreads();

    // MM5: g1 = KC^T @ DX1 -> store -g1
    mm64_tc<true, false>(KCh, KCl, HHh, HHl, acc, m0, n0, g, tg);
#pragma unroll
    for (int ni = 0; ni < 4; ni++) {
        int col = n0 + ni * 8 + 2 * tg;
        float2 v0 = {-acc[ni][0], -acc[ni][1]};
        float2 v1 = {-acc[ni][2], -acc[ni][3]};
        *(float2*)(g_g1 + gbase + (m0 + g) * 64 + col) = v0;
        *(float2*)(g_g1 + gbase + (m0 + 8 + g) * 64 + col) = v1;
    }
}

// ---------------- K5: double assoc-scan over n=128 chunks ----------------
__global__ __launch_bounds__(256) void scan_kernel(const float* __restrict__ w1,
                                                   const float* __restrict__ w2) {
    int bh = blockIdx.y;
    int idx = blockIdx.x * 256 + threadIdx.x;
    int b = bh >> 3, h = bh & 7;
    float w1v = w1[idx], w2v = w2[idx];
    float m1 = 0.f, u1 = 0.f, m2 = 0.f, u2 = 0.f;
    size_t base = ((size_t)bh * N_) * 4096 + idx;
    for (int nn = 0; nn < N_; nn++) {
        float mg = g_mom[((size_t)b * N_ + nn) * H_ + h];
        float dc = g_dec[((size_t)b * N_ + nn) * H_ + h];
        size_t off = base + (size_t)nn * 4096;
        float s1 = g_g1[off], s2 = g_g2[off];
        m1 = mg * m1 + s1; u1 = (1.f - dc) * u1 + m1; g_g1[off] = w1v + u1;
        m2 = mg * m2 + s2; u2 = (1.f - dc) * u2 + m2; g_g2[off] = w2v + u2;
    }
}

// ---------------- zero first 63 rows of packed vals per batch ----------------
__global__ void zero_pad_kernel() {
    int idx = blockIdx.x * 256 + threadIdx.x;
    const int per = 63 * DIM2_;
    if (idx < B_ * per) {
        int b = idx / per, r = idx % per;
        g_vhp[(size_t)b * T_ * DIM2_ + r] = 0u;
        g_vlp[(size_t)b * T_ * DIM2_ + r] = 0u;
    }
}

// ---------------- K6: retrieve (tensor cores, 3x tf32; emits packed bf16 vals) ----------------
#define RT_SMEM (6 * BUF * 4)
__global__ __launch_bounds__(256, 2) void retrieve_tc(const float* __restrict__ gamma) {
    int id = blockIdx.x;
    int bh = id >> 7, nn = id & 127;
    int b = bh >> 3, h = bh & 7;
    extern __shared__ uint32_t smu[];
    uint32_t* Qh  = smu;
    uint32_t* Ql  = smu + BUF;
    uint32_t* HHh = smu + 2 * BUF;   // W1eff first, then HH
    uint32_t* HHl = smu + 3 * BUF;
    uint32_t* W2h = smu + 4 * BUF;
    uint32_t* W2l = smu + 5 * BUF;
    __shared__ float rowp[64][2];
    __shared__ float gam[64];
    __shared__ float rscale[64];
    int tid = threadIdx.x;
    int j0 = nn * C_;
    size_t gbase = (size_t)id * 4096;
    if (tid < 64) gam[tid] = gamma[h * 64 + tid] + 1.f;
    for (int idx = tid; idx < 4096; idx += 256) {
        int ci = idx >> 6, a = idx & 63;
        int i = j0 + ci + 63;
        float qv = (i < T_) ? g_q[((size_t)b * T_ + i) * DIM_ + h * 64 + a] : 0.f;
        uint32_t hi = f2tf(qv);
        Qh[ci * CLD + a] = hi; Ql[ci * CLD + a] = f2tf(qv - __uint_as_float(hi));
        float e1 = g_g1[gbase + idx];
        hi = f2tf(e1);
        HHh[ci * CLD + a] = hi; HHl[ci * CLD + a] = f2tf(e1 - __uint_as_float(hi));
        float e2 = g_g2[gbase + idx];
        hi = f2tf(e2);
        W2h[ci * CLD + a] = hi; W2l[ci * CLD + a] = f2tf(e2 - __uint_as_float(hi));
    }
    __syncthreads();
    int lane = tid & 31, warp = tid >> 5;
    int m0 = (warp >> 1) * 16, n0 = (warp & 1) * 32;
    int g = lane >> 2, tg = lane & 3;
    float acc[4][4];

    // MM1: X1 = Q @ W1eff ; HH = silu(X1)
    mm64_tc<false, false>(Qh, Ql, HHh, HHl, acc, m0, n0, g, tg);
    __syncthreads();
#pragma unroll
    for (int ni = 0; ni < 4; ni++)
#pragma unroll
        for (int e = 0; e < 4; e++) {
            int row = FRAG_ROW(e), col = FRAG_COL(ni, e);
            float x = acc[ni][e];
            float hv = x * sigmoidf_(x);
            uint32_t hi = f2tf(hv);
            HHh[row * CLD + col] = hi;
            HHl[row * CLD + col] = f2tf(hv - __uint_as_float(hi));
        }
    __syncthreads();

    // MM2: Y = HH @ W2eff (stays in acc)
    mm64_tc<false, false>(HHh, HHl, W2h, W2l, acc, m0, n0, g, tg);

    // per-row sum of squares via shfl over tg lanes
    float ss0 = 0.f, ss1 = 0.f;
#pragma unroll
    for (int ni = 0; ni < 4; ni++) {
        ss0 += acc[ni][0] * acc[ni][0] + acc[ni][1] * acc[ni][1];
        ss1 += acc[ni][2] * acc[ni][2] + acc[ni][3] * acc[ni][3];
    }
#pragma unroll
    for (int o = 1; o < 4; o <<= 1) {
        ss0 += __shfl_xor_sync(0xffffffffu, ss0, o);
        ss1 += __shfl_xor_sync(0xffffffffu, ss1, o);
    }
    if (tg == 0) {
        rowp[m0 + g][warp & 1] = ss0;
        rowp[m0 + 8 + g][warp & 1] = ss1;
    }
    __syncthreads();
    if (tid < 64) {
        int i = j0 + tid + 63;
        float gate = (i < T_) ? g_gate[((size_t)b * T_ + i) * H_ + h] : 0.f;
        float tot = rowp[tid][0] + rowp[tid][1];
        rscale[tid] = rsqrtf(tot * (1.f / 64.f) + EPSV) * gate;
    }
    __syncthreads();

    // scale + gamma, emit packed bf16 hi/lo vals (adjacent column pairs)
#pragma unroll
    for (int ni = 0; ni < 4; ni++) {
        int col = n0 + ni * 8 + 2 * tg;
        float ga0 = gam[col], ga1 = gam[col + 1];
#pragma unroll
        for (int half = 0; half < 2; half++) {
            int row = m0 + g + half * 8;
            int i = j0 + row + 63;
            if (i < T_) {
                float rs = rscale[row];
                float v0 = acc[ni][half * 2 + 0] * rs * ga0;
                float v1 = acc[ni][half * 2 + 1] * rs * ga1;
                size_t oidx = ((size_t)b * T_ + i) * DIM2_ + ((h * 64 + col) >> 1);
                g_vhp[oidx] = pack_bf2(v0, v1);
                g_vlp[oidx] = pack_bf2(v0 - bf16f(v0), v1 - bf16f(v1));
            }
        }
    }
}

// ---------------- launch ----------------
extern "C" void kernel_launch(void* const* d_in, const int* in_sizes, int n_in,
                              void* d_out, int out_size) {
    const float* seq      = (const float*)d_in[0];
    const float* w1       = (const float*)d_in[1];
    const float* w2       = (const float*)d_in[2];
    const float* Wq       = (const float*)d_in[3];
    const float* Wkv      = (const float*)d_in[4];
    const float* Wstep    = (const float*)d_in[5];
    const float* Wmom     = (const float*)d_in[6];
    const float* Wdecay   = (const float*)d_in[7];
    const float* Wgate    = (const float*)d_in[8];
    const float* Wcombine = (const float*)d_in[9];
    const float* gamma    = (const float*)d_in[10];
    float* out = (float*)d_out;
    (void)in_sizes; (void)n_in; (void)out_size;

    cudaFuncSetAttribute(gemm_bf16, cudaFuncAttributeMaxDynamicSharedMemorySize, GEMM_SMEM);
    cudaFuncSetAttribute(chunk_grad_tc, cudaFuncAttributeMaxDynamicSharedMemorySize, CG_SMEM);
    cudaFuncSetAttribute(retrieve_tc, cudaFuncAttributeMaxDynamicSharedMemorySize, RT_SMEM);

    uint32_t *p_shp, *p_slp, *p_vhp, *p_vlp;
    uint32_t *p_wkvh, *p_wkvl, *p_wqh, *p_wql, *p_wch, *p_wcl;
    float *p_kv, *p_q;
    cudaGetSymbolAddress((void**)&p_shp, g_shp);
    cudaGetSymbolAddress((void**)&p_slp, g_slp);
    cudaGetSymbolAddress((void**)&p_vhp, g_vhp);
    cudaGetSymbolAddress((void**)&p_vlp, g_vlp);
    cudaGetSymbolAddress((void**)&p_wkvh, g_wkvh);
    cudaGetSymbolAddress((void**)&p_wkvl, g_wkvl);
    cudaGetSymbolAddress((void**)&p_wqh, g_wqh);
    cudaGetSymbolAddress((void**)&p_wql, g_wql);
    cudaGetSymbolAddress((void**)&p_wch, g_wch);
    cudaGetSymbolAddress((void**)&p_wcl, g_wcl);
    cudaGetSymbolAddress((void**)&p_kv, g_kv);
    cudaGetSymbolAddress((void**)&p_q, g_q);

    rmsnorm_kernel<<<B_ * T_, 256>>>(seq);
    cvtpack_kernel<<<(DIM2_ * 2 * DIM_ + 255) / 256, 256>>>(Wkv, p_wkvh, p_wkvl, DIM2_, 2 * DIM_);
    cvtpack_kernel<<<(DIM2_ * DIM_ + 255) / 256, 256>>>(Wq, p_wqh, p_wql, DIM2_, DIM_);
    cvtpack_kernel<<<(DIM2_ * DIM_ + 255) / 256, 256>>>(Wcombine, p_wch, p_wcl, DIM2_, DIM_);
    proj_kernel<<<B_ * N_, 256>>>(Wstep, Wgate, Wmom, Wdecay);
    gemm_bf16<<<dim3(2 * DIM_ / 128, B_ * T_ / 128), 256, GEMM_SMEM>>>(
        p_shp, p_slp, p_wkvh, p_wkvl, p_kv, B_ * T_, 2 * DIM_, DIM2_);
    gemm_bf16<<<dim3(DIM_ / 128, B_ * T_ / 128), 256, GEMM_SMEM>>>(
        p_shp, p_slp, p_wqh, p_wql, p_q, B_ * T_, DIM_, DIM2_);
    chunk_grad_tc<<<BH_ * N_, 256, CG_SMEM>>>(w1, w2);
    scan_kernel<<<dim3(16, BH_), 256>>>(w1, w2);
    zero_pad_kernel<<<(B_ * 63 * DIM2_ + 255) / 256, 256>>>();
    retrieve_tc<<<BH_ * N_, 256, RT_SMEM>>>(gamma);
    gemm_bf16<<<dim3(DIM_ / 128, B_ * T_ / 128), 256, GEMM_SMEM>>>(
        p_vhp, p_vlp, p_wch, p_wcl, out, B_ * T_, DIM_, DIM2_);
}

// round 13
// speedup vs baseline: 1.6207x; 1.2066x over previous
#include <cuda_runtime.h>
#include <cuda_bf16.h>
#include <cstdint>
#include <cstddef>

#define B_ 4
#define T_ 8192
#define DIM_ 512
#define DIM2_ 256
#define H_ 8
#define D_ 64
#define C_ 64
#define N_ 128
#define BH_ 32
#define EPSV 1.1920929e-07f
#define MAX_LR 0.01f

// ---------------- scratch (static device globals; no allocations) ----------------
__device__ float g_s  [(size_t)B_*T_*DIM_];     // rmsnorm(seq) fp32 (for proj)
__device__ uint32_t g_shp[(size_t)B_*T_*DIM2_]; // rmsnorm(seq) bf16x2 hi (k-paired)
__device__ uint32_t g_slp[(size_t)B_*T_*DIM2_]; // bf16x2 lo
__device__ float g_kv [(size_t)B_*T_*2*DIM_];   // [k | v]
__device__ float g_q  [(size_t)B_*T_*DIM_];     // s @ Wq
__device__ float g_g1 [(size_t)BH_*N_*D_*D_];   // -grad w1 -> W1eff after scan
__device__ float g_g2 [(size_t)BH_*N_*D_*D_];   // -grad w2 -> W2eff after scan
__device__ uint32_t g_vhp[(size_t)B_*T_*DIM2_]; // merged vals bf16x2 hi
__device__ uint32_t g_vlp[(size_t)B_*T_*DIM2_]; // bf16x2 lo
__device__ float g_lr  [(size_t)B_*T_*H_];
__device__ float g_gate[(size_t)B_*T_*H_];
__device__ float g_mom [(size_t)B_*N_*H_];
__device__ float g_dec [(size_t)B_*N_*H_];
// preconverted weights, bf16x2 k-paired hi/lo
__device__ uint32_t g_wkvh[DIM2_*2*DIM_], g_wkvl[DIM2_*2*DIM_];
__device__ uint32_t g_wqh [DIM2_*DIM_],   g_wql [DIM2_*DIM_];
__device__ uint32_t g_wch [DIM2_*DIM_],   g_wcl [DIM2_*DIM_];

__device__ __forceinline__ float sigmoidf_(float x) { return 1.f / (1.f + expf(-x)); }

__device__ __forceinline__ uint32_t f2tf(float x) {
    uint32_t r;
    asm("cvt.rna.tf32.f32 %0, %1;" : "=r"(r) : "f"(x));
    return r;
}

__device__ __forceinline__ float bf16f(float x) {
    return __bfloat162float(__float2bfloat16(x));
}

// pack two floats to bf16x2: e0 -> low 16 bits, e1 -> high
__device__ __forceinline__ uint32_t pack_bf2(float e0, float e1) {
    uint32_t r;
    asm("cvt.rn.bf16x2.f32 %0, %1, %2;" : "=r"(r) : "f"(e1), "f"(e0));
    return r;
}

__device__ __forceinline__ void mma_tf32(float c[4], const uint32_t a[4],
                                         uint32_t b0, uint32_t b1) {
    asm volatile(
        "mma.sync.aligned.m16n8k8.row.col.f32.tf32.tf32.f32 "
        "{%0,%1,%2,%3},{%4,%5,%6,%7},{%8,%9},{%0,%1,%2,%3};"
        : "+f"(c[0]), "+f"(c[1]), "+f"(c[2]), "+f"(c[3])
        : "r"(a[0]), "r"(a[1]), "r"(a[2]), "r"(a[3]), "r"(b0), "r"(b1));
}

__device__ __forceinline__ void mma_bf16(float c[4], const uint32_t a[4],
                                         uint32_t b0, uint32_t b1) {
    asm volatile(
        "mma.sync.aligned.m16n8k16.row.col.f32.bf16.bf16.f32 "
        "{%0,%1,%2,%3},{%4,%5,%6,%7},{%8,%9},{%0,%1,%2,%3};"
        : "+f"(c[0]), "+f"(c[1]), "+f"(c[2]), "+f"(c[3])
        : "r"(a[0]), "r"(a[1]), "r"(a[2]), "r"(a[3]), "r"(b0), "r"(b1));
}

__device__ __forceinline__ void cp16(uint32_t dst, const void* src) {
    asm volatile("cp.async.cg.shared.global [%0], [%1], 16;" :: "r"(dst), "l"(src));
}

// ---------------- K1: rmsnorm over dim=512, emits fp32 + packed bf16 hi/lo ----------------
__global__ __launch_bounds__(256) void rmsnorm_kernel(const float* __restrict__ seq) {
    size_t row = blockIdx.x;
    const float2* in2 = (const float2*)(seq + row * DIM_);
    int tid = threadIdx.x;
    float2 v = in2[tid];
    float ss = v.x * v.x + v.y * v.y;
#pragma unroll
    for (int o = 16; o; o >>= 1) ss += __shfl_xor_sync(0xffffffffu, ss, o);
    __shared__ float wsum[8];
    if ((tid & 31) == 0) wsum[tid >> 5] = ss;
    __syncthreads();
    float tot = 0.f;
#pragma unroll
    for (int w = 0; w < 8; w++) tot += wsum[w];
    float sc = rsqrtf(tot * (1.f / DIM_) + EPSV);
    float o0 = v.x * sc, o1 = v.y * sc;
    ((float2*)(g_s + row * DIM_))[tid] = make_float2(o0, o1);
    size_t pb = row * DIM2_ + tid;
    g_shp[pb] = pack_bf2(o0, o1);
    g_slp[pb] = pack_bf2(o0 - bf16f(o0), o1 - bf16f(o1));
}

// ---------------- weight preconvert: pack along K into bf16x2 hi/lo ----------------
__global__ void cvtpack_kernel(const float* __restrict__ src, uint32_t* __restrict__ dh,
                               uint32_t* __restrict__ dl, int K2, int N) {
    int i = blockIdx.x * 256 + threadIdx.x;
    if (i < K2 * N) {
        int k2 = i / N, n = i - k2 * N;
        float e0 = src[(size_t)(2 * k2) * N + n];
        float e1 = src[(size_t)(2 * k2 + 1) * N + n];
        dh[i] = pack_bf2(e0, e1);
        dl[i] = pack_bf2(e0 - bf16f(e0), e1 - bf16f(e1));
    }
}

// ---------------- K2: per-token lr/gate projections + per-chunk mom/decay ----------------
__global__ __launch_bounds__(256) void proj_kernel(const float* __restrict__ Wstep,
                                                   const float* __restrict__ Wgate,
                                                   const float* __restrict__ Wmom,
                                                   const float* __restrict__ Wdecay) {
    int blk = blockIdx.x;              // b*N_ + nn
    int b = blk >> 7, nn = blk & 127;
    size_t tb = (size_t)b * T_ + (size_t)nn * C_;
    int tid = threadIdx.x, lane = tid & 31, w = tid >> 5;

    for (int tk = w; tk < C_; tk += 8) {
        const float* srow = g_s + (tb + tk) * DIM_;
        float acc[16];
#pragma unroll
        for (int q = 0; q < 16; q++) acc[q] = 0.f;
        for (int p = lane; p < DIM_; p += 32) {
            float sv = srow[p];
            const float* ws = Wstep + p * H_;
            const float* wg = Wgate + p * H_;
#pragma unroll
            for (int hh = 0; hh < 8; hh++) {
                acc[hh]     += sv * ws[hh];
                acc[8 + hh] += sv * wg[hh];
            }
        }
#pragma unroll
        for (int q = 0; q < 16; q++)
#pragma unroll
            for (int o = 16; o; o >>= 1) acc[q] += __shfl_xor_sync(0xffffffffu, acc[q], o);
        if (lane == 0) {
#pragma unroll
            for (int hh = 0; hh < 8; hh++) {
                g_lr  [(tb + tk) * H_ + hh] = sigmoidf_(acc[hh]) * MAX_LR;
                g_gate[(tb + tk) * H_ + hh] = sigmoidf_(acc[8 + hh]);
            }
        }
    }

    __shared__ float ssum[DIM_];
    for (int p = tid; p < DIM_; p += 256) {
        float a = 0.f;
        for (int tk = 0; tk < C_; tk++) a += g_s[(tb + tk) * DIM_ + p];
        ssum[p] = a * (1.f / C_);
    }
    __syncthreads();
    if (w < 8) {
        float am = 0.f, ad = 0.f;
        for (int p = lane; p < DIM_; p += 32) {
            am += ssum[p] * Wmom[p * H_ + w];
            ad += ssum[p] * Wdecay[p * H_ + w];
        }
#pragma unroll
        for (int o = 16; o; o >>= 1) {
            am += __shfl_xor_sync(0xffffffffu, am, o);
            ad += __shfl_xor_sync(0xffffffffu, ad, o);
        }
        if (lane == 0) {
            g_mom[((size_t)b * N_ + nn) * H_ + w] = sigmoidf_(am);
            g_dec[((size_t)b * N_ + nn) * H_ + w] = sigmoidf_(ad);
        }
    }
}

// ---------------- gemm_bf16: cp.async double-buffered, 3-term bf16 split ----------------
// A packed [M][K2] u32 (bf16x2 along k), B packed [K2][N] u32, C fp32 [M][N]
#define GA_LD 20
#define GB_LD 136
#define GA_SZ (128 * GA_LD)
#define GB_SZ (16 * GB_LD)
#define GSTAGE (2 * GA_SZ + 2 * GB_SZ)
#define GEMM_SMEM (2 * GSTAGE * 4)

__device__ __forceinline__ void gemm_issue(uint32_t sbase, const uint32_t* __restrict__ Ah,
                                           const uint32_t* __restrict__ Al,
                                           const uint32_t* __restrict__ Bh,
                                           const uint32_t* __restrict__ Bl,
                                           int brow, int bcol, int kt2, int K2, int N, int tid) {
    int ra = tid >> 2, ca = (tid & 3) << 2;
    int rb = tid >> 5, cb = (tid & 31) << 2;
#pragma unroll
    for (int p = 0; p < 2; p++) {
        int r = p * 64 + ra;
        size_t ga = (size_t)(brow + r) * K2 + kt2 + ca;
        uint32_t da = sbase + (r * GA_LD + ca) * 4;
        cp16(da, Ah + ga);
        cp16(da + GA_SZ * 4, Al + ga);
        int r2 = p * 8 + rb;
        size_t gb = (size_t)(kt2 + r2) * N + bcol + cb;
        uint32_t db = sbase + (2 * GA_SZ + r2 * GB_LD + cb) * 4;
        cp16(db, Bh + gb);
        cp16(db + GB_SZ * 4, Bl + gb);
    }
}

__global__ __launch_bounds__(256, 2) void gemm_bf16(const uint32_t* __restrict__ Ah,
                                                    const uint32_t* __restrict__ Al,
                                                    const uint32_t* __restrict__ Bh,
                                                    const uint32_t* __restrict__ Bl,
                                                    float* __restrict__ C,
                                                    int M, int N, int K2) {
    extern __shared__ uint32_t smem_u[];
    int tid = threadIdx.x;
    int lane = tid & 31, warp = tid >> 5;
    int brow = blockIdx.y * 128, bcol = blockIdx.x * 128;
    int wm = (warp >> 1) * 32, wn = (warp & 1) * 64;
    int g = lane >> 2, tg = lane & 3;
    uint32_t sbase = (uint32_t)__cvta_generic_to_shared(smem_u);

    float acc[2][8][4];
#pragma unroll
    for (int mi = 0; mi < 2; mi++)
#pragma unroll
        for (int ni = 0; ni < 8; ni++)
#pragma unroll
            for (int e = 0; e < 4; e++) acc[mi][ni][e] = 0.f;

    gemm_issue(sbase, Ah, Al, Bh, Bl, brow, bcol, 0, K2, N, tid);
    asm volatile("cp.async.commit_group;");

    int KT = K2 >> 4;
    for (int t = 0; t < KT; t++) {
        if (t + 1 < KT) {
            gemm_issue(sbase + ((t + 1) & 1) * GSTAGE * 4, Ah, Al, Bh, Bl,
                       brow, bcol, (t + 1) << 4, K2, N, tid);
            asm volatile("cp.async.commit_group;");
            asm volatile("cp.async.wait_group 1;");
        } else {
            asm volatile("cp.async.wait_group 0;");
        }
        __syncthreads();
        const uint32_t* st = smem_u + (t & 1) * GSTAGE;
        const uint32_t* sAh = st;
        const uint32_t* sAl = st + GA_SZ;
        const uint32_t* sBh = st + 2 * GA_SZ;
        const uint32_t* sBl = st + 2 * GA_SZ + GB_SZ;
#pragma unroll
        for (int kh = 0; kh < 2; kh++) {
            int k8 = kh * 8;
            uint32_t ah[2][4], al[2][4];
#pragma unroll
            for (int mi = 0; mi < 2; mi++) {
                int r0 = (wm + mi * 16 + g) * GA_LD + k8 + tg;
                int r1 = r0 + 8 * GA_LD;
                ah[mi][0] = sAh[r0];     ah[mi][1] = sAh[r1];
                ah[mi][2] = sAh[r0 + 4]; ah[mi][3] = sAh[r1 + 4];
                al[mi][0] = sAl[r0];     al[mi][1] = sAl[r1];
                al[mi][2] = sAl[r0 + 4]; al[mi][3] = sAl[r1 + 4];
            }
#pragma unroll
            for (int ni = 0; ni < 8; ni++) {
                int nb = (k8 + tg) * GB_LD + wn + ni * 8 + g;
                uint32_t bh0 = sBh[nb], bh1 = sBh[nb + 4 * GB_LD];
                uint32_t bl0 = sBl[nb], bl1 = sBl[nb + 4 * GB_LD];
#pragma unroll
                for (int mi = 0; mi < 2; mi++) {
                    mma_bf16(acc[mi][ni], ah[mi], bh0, bh1);
                    mma_bf16(acc[mi][ni], ah[mi], bl0, bl1);
                    mma_bf16(acc[mi][ni], al[mi], bh0, bh1);
                }
            }
        }
        __syncthreads();
    }

#pragma unroll
    for (int mi = 0; mi < 2; mi++)
#pragma unroll
        for (int ni = 0; ni < 8; ni++) {
            int r = brow + wm + mi * 16 + g;
            int cx = bcol + wn + ni * 8 + tg * 2;
            float2 lo = {acc[mi][ni][0], acc[mi][ni][1]};
            float2 hi = {acc[mi][ni][2], acc[mi][ni][3]};
            *(float2*)(C + (size_t)r * N + cx) = lo;
            *(float2*)(C + (size_t)(r + 8) * N + cx) = hi;
        }
}

// ---------------- tensor-core 64x64x64 from smem tf32 hi/lo, selectable terms ----------------
// Terms: always ah*bh; +ah*bl if BL; +al*bh if AL.
#define CLD 68
#define BUF (64 * CLD)

template <bool TA, bool TB, bool AL, bool BL>
__device__ __forceinline__ void mm64_tc(const uint32_t* __restrict__ Ah,
                                        const uint32_t* __restrict__ Al,
                                        const uint32_t* __restrict__ Bh,
                                        const uint32_t* __restrict__ Bl,
                                        float acc[4][4], int m0, int n0, int g, int tg) {
#pragma unroll
    for (int ni = 0; ni < 4; ni++)
#pragma unroll
        for (int e = 0; e < 4; e++) acc[ni][e] = 0.f;
#pragma unroll 2
    for (int k8 = 0; k8 < 64; k8 += 8) {
        uint32_t ah[4], al[4] = {0, 0, 0, 0};
        if (!TA) {
            int ba = (m0 + g) * CLD + k8 + tg;
            ah[0] = Ah[ba]; ah[1] = Ah[ba + 8 * CLD]; ah[2] = Ah[ba + 4]; ah[3] = Ah[ba + 8 * CLD + 4];
            if (AL) {
                al[0] = Al[ba]; al[1] = Al[ba + 8 * CLD]; al[2] = Al[ba + 4]; al[3] = Al[ba + 8 * CLD + 4];
            }
        } else {
            int ba = (k8 + tg) * CLD + m0 + g;
            ah[0] = Ah[ba]; ah[1] = Ah[ba + 8]; ah[2] = Ah[ba + 4 * CLD]; ah[3] = Ah[ba + 4 * CLD + 8];
            if (AL) {
                al[0] = Al[ba]; al[1] = Al[ba + 8]; al[2] = Al[ba + 4 * CLD]; al[3] = Al[ba + 4 * CLD + 8];
            }
        }
#pragma unroll
        for (int ni = 0; ni < 4; ni++) {
            uint32_t bh0, bh1, bl0 = 0, bl1 = 0;
            if (!TB) {
                int bb = (k8 + tg) * CLD + n0 + ni * 8 + g;
                bh0 = Bh[bb]; bh1 = Bh[bb + 4 * CLD];
                if (BL) { bl0 = Bl[bb]; bl1 = Bl[bb + 4 * CLD]; }
            } else {
                int bb = (n0 + ni * 8 + g) * CLD + k8 + tg;
                bh0 = Bh[bb]; bh1 = Bh[bb + 4];
                if (BL) { bl0 = Bl[bb]; bl1 = Bl[bb + 4]; }
            }
            mma_tf32(acc[ni], ah, bh0, bh1);
            if (BL) mma_tf32(acc[ni], ah, bl0, bl1);
            if (AL) mma_tf32(acc[ni], al, bh0, bh1);
        }
    }
}

// fragment (row, col): e0=(g,2tg) e1=(g,2tg+1) e2=(g+8,2tg) e3=(g+8,2tg+1)
#define FRAG_ROW(e) (m0 + g + ((e) >> 1 ? 8 : 0))
#define FRAG_COL(ni, e) (n0 + (ni) * 8 + 2 * tg + ((e) & 1))

// ---------------- K4: per-chunk MLP gradients (6 smem bufs -> 2 CTAs/SM) ----------------
// Buffers: KCh | HHh (W1h -> HH hi -> DX1 hi) | HHl (W1l -> HH lo -> DX1 lo) | W2h | W2l | G2h
#define CG_SMEM (6 * BUF * 4)
__global__ __launch_bounds__(256, 2) void chunk_grad_tc(const float* __restrict__ w1,
                                                        const float* __restrict__ w2) {
    int id = blockIdx.x;               // bh*N_ + nn
    int bh = id >> 7, nn = id & 127;
    int b = bh >> 3, h = bh & 7;
    size_t tb = (size_t)b * T_ + (size_t)nn * C_;
    extern __shared__ uint32_t smu2[];
    uint32_t* KCh = smu2;
    uint32_t* HHh = smu2 + BUF;
    uint32_t* HHl = smu2 + 2 * BUF;
    uint32_t* W2h = smu2 + 3 * BUF;
    uint32_t* W2l = smu2 + 4 * BUF;
    uint32_t* G2h = smu2 + 5 * BUF;
    __shared__ float lrs[64];
    int tid = threadIdx.x;
    if (tid < 64) lrs[tid] = g_lr[(tb + tid) * H_ + h];
    for (int idx = tid; idx < 4096; idx += 256) {
        int i = idx >> 6, j = idx & 63;
        float kc = g_kv[(tb + i) * (2 * DIM_) + h * 64 + j];
        KCh[i * CLD + j] = f2tf(kc);
        float a1 = w1[idx];
        uint32_t hi = f2tf(a1);
        HHh[i * CLD + j] = hi; HHl[i * CLD + j] = f2tf(a1 - __uint_as_float(hi));
        float a2 = w2[idx];
        hi = f2tf(a2);
        W2h[i * CLD + j] = hi; W2l[i * CLD + j] = f2tf(a2 - __uint_as_float(hi));
    }
    __syncthreads();
    int lane = tid & 31, warp = tid >> 5;
    int m0 = (warp >> 1) * 16, n0 = (warp & 1) * 32;
    int g = lane >> 2, tg = lane & 3;
    float acc[4][4], x1s[4][4];

    // MM1: X1 = KC(hi) @ W1(hi/lo); X1 kept in regs; HH = silu(X1) hi/lo
    mm64_tc<false, false, false, true>(KCh, nullptr, HHh, HHl, acc, m0, n0, g, tg);
    __syncthreads();   // all warps done reading W1 before HH overwrite
#pragma unroll
    for (int ni = 0; ni < 4; ni++)
#pragma unroll
        for (int e = 0; e < 4; e++) {
            int row = FRAG_ROW(e), col = FRAG_COL(ni, e);
            float x = acc[ni][e];
            x1s[ni][e] = x;
            float hv = x * sigmoidf_(x);
            uint32_t hi = f2tf(hv);
            HHh[row * CLD + col] = hi;
            HHl[row * CLD + col] = f2tf(hv - __uint_as_float(hi));
        }
    __syncthreads();

    // MM2: X2 = HH(hi/lo) @ W2(hi/lo) [3-term] ; G2 = (2 lr / 64)(X2 - v), hi only
    mm64_tc<false, false, true, true>(HHh, HHl, W2h, W2l, acc, m0, n0, g, tg);
#pragma unroll
    for (int ni = 0; ni < 4; ni++)
#pragma unroll
        for (int e = 0; e < 4; e++) {
            int row = FRAG_ROW(e), col = FRAG_COL(ni, e);
            float vc = g_kv[(tb + row) * (2 * DIM_) + DIM_ + h * 64 + col];
            float gg = (2.f / 64.f) * lrs[row] * (acc[ni][e] - vc);
            G2h[row * CLD + col] = f2tf(gg);
        }
    __syncthreads();

    // MM3: g2 = HH^T(hi/lo) @ G2(hi) -> store -g2
    mm64_tc<true, false, true, false>(HHh, HHl, G2h, nullptr, acc, m0, n0, g, tg);
    size_t gbase = (size_t)id * 4096;
#pragma unroll
    for (int ni = 0; ni < 4; ni++) {
        int col = n0 + ni * 8 + 2 * tg;
        float2 v0 = {-acc[ni][0], -acc[ni][1]};
        float2 v1 = {-acc[ni][2], -acc[ni][3]};
        *(float2*)(g_g2 + gbase + (m0 + g) * 64 + col) = v0;
        *(float2*)(g_g2 + gbase + (m0 + 8 + g) * 64 + col) = v1;
    }
    __syncthreads();   // HH reads done before DX1 overwrite

    // MM4: DX1 = (G2(hi) @ W2^T(hi/lo)) * silu'(X1) -> into HH bufs hi/lo
    mm64_tc<false, true, false, true>(G2h, nullptr, W2h, W2l, acc, m0, n0, g, tg);
#pragma unroll
    for (int ni = 0; ni < 4; ni++)
#pragma unroll
        for (int e = 0; e < 4; e++) {
            int row = FRAG_ROW(e), col = FRAG_COL(ni, e);
            float x = x1s[ni][e];
            float sg = sigmoidf_(x);
            float dv = acc[ni][e] * sg * (1.f + x * (1.f - sg));
            uint32_t hi = f2tf(dv);
            HHh[row * CLD + col] = hi;
            HHl[row * CLD + col] = f2tf(dv - __uint_as_float(hi));
        }
    __syncthreads();

    // MM5: g1 = KC^T(hi) @ DX1(hi/lo) -> store -g1
    mm64_tc<true, false, false, true>(KCh, nullptr, HHh, HHl, acc, m0, n0, g, tg);
#pragma unroll
    for (int ni = 0; ni < 4; ni++) {
        int col = n0 + ni * 8 + 2 * tg;
        float2 v0 = {-acc[ni][0], -acc[ni][1]};
        float2 v1 = {-acc[ni][2], -acc[ni][3]};
        *(float2*)(g_g1 + gbase + (m0 + g) * 64 + col) = v0;
        *(float2*)(g_g1 + gbase + (m0 + 8 + g) * 64 + col) = v1;
    }
}

// ---------------- K5: double assoc-scan over n=128 chunks ----------------
__global__ __launch_bounds__(256) void scan_kernel(const float* __restrict__ w1,
                                                   const float* __restrict__ w2) {
    int bh = blockIdx.y;
    int idx = blockIdx.x * 256 + threadIdx.x;
    int b = bh >> 3, h = bh & 7;
    float w1v = w1[idx], w2v = w2[idx];
    float m1 = 0.f, u1 = 0.f, m2 = 0.f, u2 = 0.f;
    size_t base = ((size_t)bh * N_) * 4096 + idx;
    for (int nn = 0; nn < N_; nn++) {
        float mg = g_mom[((size_t)b * N_ + nn) * H_ + h];
        float dc = g_dec[((size_t)b * N_ + nn) * H_ + h];
        size_t off = base + (size_t)nn * 4096;
        float s1 = g_g1[off], s2 = g_g2[off];
        m1 = mg * m1 + s1; u1 = (1.f - dc) * u1 + m1; g_g1[off] = w1v + u1;
        m2 = mg * m2 + s2; u2 = (1.f - dc) * u2 + m2; g_g2[off] = w2v + u2;
    }
}

// ---------------- zero first 63 rows of packed vals per batch ----------------
__global__ void zero_pad_kernel() {
    int idx = blockIdx.x * 256 + threadIdx.x;
    const int per = 63 * DIM2_;
    if (idx < B_ * per) {
        int b = idx / per, r = idx % per;
        g_vhp[(size_t)b * T_ * DIM2_ + r] = 0u;
        g_vlp[(size_t)b * T_ * DIM2_ + r] = 0u;
    }
}

// ---------------- K6: retrieve (tensor cores, 3x tf32; emits packed bf16 vals) ----------------
#define RT_SMEM (6 * BUF * 4)
__global__ __launch_bounds__(256, 2) void retrieve_tc(const float* __restrict__ gamma) {
    int id = blockIdx.x;
    int bh = id >> 7, nn = id & 127;
    int b = bh >> 3, h = bh & 7;
    extern __shared__ uint32_t smu3[];
    uint32_t* Qh  = smu3;
    uint32_t* Ql  = smu3 + BUF;
    uint32_t* HHh = smu3 + 2 * BUF;   // W1eff first, then HH
    uint32_t* HHl = smu3 + 3 * BUF;
    uint32_t* W2h = smu3 + 4 * BUF;
    uint32_t* W2l = smu3 + 5 * BUF;
    __shared__ float rowp[64][2];
    __shared__ float gam[64];
    __shared__ float rscale[64];
    int tid = threadIdx.x;
    int j0 = nn * C_;
    size_t gbase = (size_t)id * 4096;
    if (tid < 64) gam[tid] = gamma[h * 64 + tid] + 1.f;
    for (int idx = tid; idx < 4096; idx += 256) {
        int ci = idx >> 6, a = idx & 63;
        int i = j0 + ci + 63;
        float qv = (i < T_) ? g_q[((size_t)b * T_ + i) * DIM_ + h * 64 + a] : 0.f;
        uint32_t hi = f2tf(qv);
        Qh[ci * CLD + a] = hi; Ql[ci * CLD + a] = f2tf(qv - __uint_as_float(hi));
        float e1 = g_g1[gbase + idx];
        hi = f2tf(e1);
        HHh[ci * CLD + a] = hi; HHl[ci * CLD + a] = f2tf(e1 - __uint_as_float(hi));
        float e2 = g_g2[gbase + idx];
        hi = f2tf(e2);
        W2h[ci * CLD + a] = hi; W2l[ci * CLD + a] = f2tf(e2 - __uint_as_float(hi));
    }
    __syncthreads();
    int lane = tid & 31, warp = tid >> 5;
    int m0 = (warp >> 1) * 16, n0 = (warp & 1) * 32;
    int g = lane >> 2, tg = lane & 3;
    float acc[4][4];

    mm64_tc<false, false, true, true>(Qh, Ql, HHh, HHl, acc, m0, n0, g, tg);
    __syncthreads();
#pragma unroll
    for (int ni = 0; ni < 4; ni++)
#pragma unroll
        for (int e = 0; e < 4; e++) {
            int row = FRAG_ROW(e), col = FRAG_COL(ni, e);
            float x = acc[ni][e];
            float hv = x * sigmoidf_(x);
            uint32_t hi = f2tf(hv);
            HHh[row * CLD + col] = hi;
            HHl[row * CLD + col] = f2tf(hv - __uint_as_float(hi));
        }
    __syncthreads();

    mm64_tc<false, false, true, true>(HHh, HHl, W2h, W2l, acc, m0, n0, g, tg);

    float ss0 = 0.f, ss1 = 0.f;
#pragma unroll
    for (int ni = 0; ni < 4; ni++) {
        ss0 += acc[ni][0] * acc[ni][0] + acc[ni][1] * acc[ni][1];
        ss1 += acc[ni][2] * acc[ni][2] + acc[ni][3] * acc[ni][3];
    }
#pragma unroll
    for (int o = 1; o < 4; o <<= 1) {
        ss0 += __shfl_xor_sync(0xffffffffu, ss0, o);
        ss1 += __shfl_xor_sync(0xffffffffu, ss1, o);
    }
    if (tg == 0) {
        rowp[m0 + g][warp & 1] = ss0;
        rowp[m0 + 8 + g][warp & 1] = ss1;
    }
    __syncthreads();
    if (tid < 64) {
        int i = j0 + tid + 63;
        float gate = (i < T_) ? g_gate[((size_t)b * T_ + i) * H_ + h] : 0.f;
        float tot = rowp[tid][0] + rowp[tid][1];
        rscale[tid] = rsqrtf(tot * (1.f / 64.f) + EPSV) * gate;
    }
    __syncthreads();

#pragma unroll
    for (int ni = 0; ni < 4; ni++) {
        int col = n0 + ni * 8 + 2 * tg;
        float ga0 = gam[col], ga1 = gam[col + 1];
#pragma unroll
        for (int half = 0; half < 2; half++) {
            int row = m0 + g + half * 8;
            int i = j0 + row + 63;
            if (i < T_) {
                float rs = rscale[row];
                float v0 = acc[ni][half * 2 + 0] * rs * ga0;
                float v1 = acc[ni][half * 2 + 1] * rs * ga1;
                size_t oidx = ((size_t)b * T_ + i) * DIM2_ + ((h * 64 + col) >> 1);
                g_vhp[oidx] = pack_bf2(v0, v1);
                g_vlp[oidx] = pack_bf2(v0 - bf16f(v0), v1 - bf16f(v1));
            }
        }
    }
}

// ---------------- launch ----------------
extern "C" void kernel_launch(void* const* d_in, const int* in_sizes, int n_in,
                              void* d_out, int out_size) {
    const float* seq      = (const float*)d_in[0];
    const float* w1       = (const float*)d_in[1];
    const float* w2       = (const float*)d_in[2];
    const float* Wq       = (const float*)d_in[3];
    const float* Wkv      = (const float*)d_in[4];
    const float* Wstep    = (const float*)d_in[5];
    const float* Wmom     = (const float*)d_in[6];
    const float* Wdecay   = (const float*)d_in[7];
    const float* Wgate    = (const float*)d_in[8];
    const float* Wcombine = (const float*)d_in[9];
    const float* gamma    = (const float*)d_in[10];
    float* out = (float*)d_out;
    (void)in_sizes; (void)n_in; (void)out_size;

    cudaFuncSetAttribute(gemm_bf16, cudaFuncAttributeMaxDynamicSharedMemorySize, GEMM_SMEM);
    cudaFuncSetAttribute(chunk_grad_tc, cudaFuncAttributeMaxDynamicSharedMemorySize, CG_SMEM);
    cudaFuncSetAttribute(retrieve_tc, cudaFuncAttributeMaxDynamicSharedMemorySize, RT_SMEM);

    uint32_t *p_shp, *p_slp, *p_vhp, *p_vlp;
    uint32_t *p_wkvh, *p_wkvl, *p_wqh, *p_wql, *p_wch, *p_wcl;
    float *p_kv, *p_q;
    cudaGetSymbolAddress((void**)&p_shp, g_shp);
    cudaGetSymbolAddress((void**)&p_slp, g_slp);
    cudaGetSymbolAddress((void**)&p_vhp, g_vhp);
    cudaGetSymbolAddress((void**)&p_vlp, g_vlp);
    cudaGetSymbolAddress((void**)&p_wkvh, g_wkvh);
    cudaGetSymbolAddress((void**)&p_wkvl, g_wkvl);
    cudaGetSymbolAddress((void**)&p_wqh, g_wqh);
    cudaGetSymbolAddress((void**)&p_wql, g_wql);
    cudaGetSymbolAddress((void**)&p_wch, g_wch);
    cudaGetSymbolAddress((void**)&p_wcl, g_wcl);
    cudaGetSymbolAddress((void**)&p_kv, g_kv);
    cudaGetSymbolAddress((void**)&p_q, g_q);

    rmsnorm_kernel<<<B_ * T_, 256>>>(seq);
    cvtpack_kernel<<<(DIM2_ * 2 * DIM_ + 255) / 256, 256>>>(Wkv, p_wkvh, p_wkvl, DIM2_, 2 * DIM_);
    cvtpack_kernel<<<(DIM2_ * DIM_ + 255) / 256, 256>>>(Wq, p_wqh, p_wql, DIM2_, DIM_);
    cvtpack_kernel<<<(DIM2_ * DIM_ + 255) / 256, 256>>>(Wcombine, p_wch, p_wcl, DIM2_, DIM_);
    proj_kernel<<<B_ * N_, 256>>>(Wstep, Wgate, Wmom, Wdecay);
    gemm_bf16<<<dim3(2 * DIM_ / 128, B_ * T_ / 128), 256, GEMM_SMEM>>>(
        p_shp, p_slp, p_wkvh, p_wkvl, p_kv, B_ * T_, 2 * DIM_, DIM2_);
    gemm_bf16<<<dim3(DIM_ / 128, B_ * T_ / 128), 256, GEMM_SMEM>>>(
        p_shp, p_slp, p_wqh, p_wql, p_q, B_ * T_, DIM_, DIM2_);
    chunk_grad_tc<<<BH_ * N_, 256, CG_SMEM>>>(w1, w2);
    scan_kernel<<<dim3(16, BH_), 256>>>(w1, w2);
    zero_pad_kernel<<<(B_ * 63 * DIM2_ + 255) / 256, 256>>>();
    retrieve_tc<<<BH_ * N_, 256, RT_SMEM>>>(gamma);
    gemm_bf16<<<dim3(DIM_ / 128, B_ * T_ / 128), 256, GEMM_SMEM>>>(
        p_vhp, p_vlp, p_wch, p_wcl, out, B_ * T_, DIM_, DIM2_);
}